// round 10
// baseline (speedup 1.0000x reference)
#include <cuda_runtime.h>
#include <cuda_bf16.h>
#include <cstddef>
#include <cstdint>

#define BBATCH 8
#define CCH    256
#define NTOK   4096     // 64*64
#define NG     32
#define CPG    8
#define EPSV   1e-6f

typedef __nv_bfloat16 bf16;

// ---------------- scratch (device globals; no allocation allowed) ----------
__device__ bf16   g_hnb[(size_t)BBATCH * CCH * NTOK];   // GN out [c][n]
__device__ bf16   g_hnT[(size_t)BBATCH * NTOK * CCH];   // GN out transposed [n][c]
__device__ bf16   g_qt [(size_t)BBATCH * NTOK * CCH];   // Q^T [n][o] bf16
__device__ bf16   g_kt [(size_t)BBATCH * NTOK * CCH];   // K^T [m][o] bf16
__device__ bf16   g_vb [(size_t)BBATCH * CCH * NTOK];   // V [o][m] bf16
__device__ bf16   g_ht [(size_t)BBATCH * NTOK * CCH];   // attn out^T [n][o]
__device__ int8_t g_q8 [(size_t)BBATCH * NTOK * CCH];
__device__ int8_t g_k8 [(size_t)BBATCH * NTOK * CCH];
__device__ int8_t g_v8 [(size_t)BBATCH * CCH * NTOK];
__device__ int8_t g_p8 [(size_t)BBATCH * NTOK * NTOK];  // int8 exp(S)*32
__device__ bf16   g_wqb[CCH * CCH];
__device__ bf16   g_wkb[CCH * CCH];
__device__ bf16   g_wvb[CCH * CCH];
__device__ bf16   g_wpb[CCH * CCH];
__device__ float  g_absmax[3];   // q, k, v

#define PSCALE 32.0f

// ================= low-level helpers ========================================
__device__ __forceinline__ uint32_t smem_u32(const void* p) {
    uint32_t a;
    asm("{ .reg .u64 t; cvta.to.shared.u64 t, %1; cvt.u32.u64 %0, t; }" : "=r"(a) : "l"(p));
    return a;
}
__device__ __forceinline__ void cp_async16(uint32_t saddr, const void* gaddr) {
    asm volatile("cp.async.cg.shared.global [%0], [%1], 16;" :: "r"(saddr), "l"(gaddr));
}
#define CP_COMMIT() asm volatile("cp.async.commit_group;" ::: "memory")
#define CP_WAIT(n)  asm volatile("cp.async.wait_group %0;" :: "n"(n) : "memory")

__device__ __forceinline__ void ldsm4(uint32_t* r, uint32_t addr) {
    asm volatile("ldmatrix.sync.aligned.m8n8.x4.shared.b16 {%0,%1,%2,%3}, [%4];"
                 : "=r"(r[0]), "=r"(r[1]), "=r"(r[2]), "=r"(r[3]) : "r"(addr));
}
__device__ __forceinline__ void mma16816(float* c, const uint32_t* a, const uint32_t* b) {
    asm volatile("mma.sync.aligned.m16n8k16.row.col.f32.bf16.bf16.f32 "
                 "{%0,%1,%2,%3}, {%4,%5,%6,%7}, {%8,%9}, {%0,%1,%2,%3};"
                 : "+f"(c[0]), "+f"(c[1]), "+f"(c[2]), "+f"(c[3])
                 : "r"(a[0]), "r"(a[1]), "r"(a[2]), "r"(a[3]),
                   "r"(b[0]), "r"(b[1]));
}
__device__ __forceinline__ void mma16832s8(int* c, const uint32_t* a, const uint32_t* b) {
    asm volatile("mma.sync.aligned.m16n8k32.row.col.s32.s8.s8.s32 "
                 "{%0,%1,%2,%3}, {%4,%5,%6,%7}, {%8,%9}, {%0,%1,%2,%3};"
                 : "+r"(c[0]), "+r"(c[1]), "+r"(c[2]), "+r"(c[3])
                 : "r"(a[0]), "r"(a[1]), "r"(a[2]), "r"(a[3]),
                   "r"(b[0]), "r"(b[1]));
}

// ---------------- block reductions (blockDim == 256) -----------------------
__device__ __forceinline__ float blk_reduce_sum(float v, float* sh) {
    int lane = threadIdx.x & 31, w = threadIdx.x >> 5;
    #pragma unroll
    for (int o = 16; o; o >>= 1) v += __shfl_xor_sync(0xffffffffu, v, o);
    __syncthreads();
    if (lane == 0) sh[w] = v;
    __syncthreads();
    if (threadIdx.x == 0) {
        float r = 0.f;
        #pragma unroll
        for (int i = 0; i < 8; i++) r += sh[i];
        sh[0] = r;
    }
    __syncthreads();
    return sh[0];
}

// ---------------- init scales ------------------------------------------------
__global__ void init_scales_kernel() {
    if (threadIdx.x < 3) ((int*)g_absmax)[threadIdx.x] = 0;
}

// ---------------- absmax (deterministic atomicMax on float bits) ------------
__global__ __launch_bounds__(256)
void absmax_kernel(const bf16* __restrict__ src, size_t n2, float* __restrict__ out) {
    float m = 0.f;
    for (size_t i = (size_t)blockIdx.x * 256 + threadIdx.x; i < n2; i += (size_t)gridDim.x * 256) {
        __nv_bfloat162 v = ((const __nv_bfloat162*)src)[i];
        m = fmaxf(m, fmaxf(fabsf(__bfloat162float(v.x)), fabsf(__bfloat162float(v.y))));
    }
    #pragma unroll
    for (int o = 16; o; o >>= 1) m = fmaxf(m, __shfl_xor_sync(0xffffffffu, m, o));
    __shared__ float sh[8];
    if ((threadIdx.x & 31) == 0) sh[threadIdx.x >> 5] = m;
    __syncthreads();
    if (threadIdx.x == 0) {
        float r = sh[0];
        #pragma unroll
        for (int i = 1; i < 8; i++) r = fmaxf(r, sh[i]);
        atomicMax((int*)out, __float_as_int(r));   // nonneg floats: int order == float order
    }
}

// ---------------- bf16 -> int8 quantize (per-tensor scale) -------------------
__global__ __launch_bounds__(256)
void quant_kernel(const bf16* __restrict__ src, int8_t* __restrict__ dst,
                  const float* __restrict__ am) {
    const float s = 127.f / am[0];
    size_t i = (size_t)blockIdx.x * 256 + threadIdx.x;   // 4 elems per thread
    __nv_bfloat162 a = ((const __nv_bfloat162*)src)[2 * i + 0];
    __nv_bfloat162 b = ((const __nv_bfloat162*)src)[2 * i + 1];
    int v0 = __float2int_rn(__bfloat162float(a.x) * s);
    int v1 = __float2int_rn(__bfloat162float(a.y) * s);
    int v2 = __float2int_rn(__bfloat162float(b.x) * s);
    int v3 = __float2int_rn(__bfloat162float(b.y) * s);
    char4 c;
    c.x = (char)max(-127, min(127, v0));
    c.y = (char)max(-127, min(127, v1));
    c.z = (char)max(-127, min(127, v2));
    c.w = (char)max(-127, min(127, v3));
    ((char4*)dst)[i] = c;
}

// ---------------- GroupNorm (bf16 out) --------------------------------------
__global__ __launch_bounds__(256)
void gn_kernel(const float* __restrict__ x, const float* __restrict__ gsc,
               const float* __restrict__ gbi) {
    __shared__ float sh[8];
    int b = blockIdx.x >> 5;
    int g = blockIdx.x & 31;
    const size_t base = ((size_t)b * CCH + (size_t)g * CPG) * NTOK;
    const float* xp = x + base;
    const int total = CPG * NTOK;
    float s = 0.f, ss = 0.f;
    for (int i = threadIdx.x; i < total; i += 256) {
        float v = xp[i];
        s += v; ss += v * v;
    }
    s  = blk_reduce_sum(s,  sh);
    ss = blk_reduce_sum(ss, sh);
    const float inv_n = 1.f / (float)total;
    float mean = s * inv_n;
    float var  = ss * inv_n - mean * mean;
    float rstd = rsqrtf(var + EPSV);
    for (int i = threadIdx.x; i < total; i += 256) {
        int c = g * CPG + (i >> 12);
        g_hnb[base + i] = __float2bfloat16((xp[i] - mean) * rstd * gsc[c] + gbi[c]);
    }
}

// ---------------- bf16 transpose [C][N] -> [N][C] ----------------------------
__global__ __launch_bounds__(256)
void transpose_kernel(const bf16* __restrict__ src, bf16* __restrict__ dst) {
    __shared__ bf16 tile[64][65];
    const int b  = blockIdx.z;
    const int n0 = blockIdx.x * 64;
    const int c0 = blockIdx.y * 64;
    const bf16* sb = src + (size_t)b * CCH * NTOK;
    bf16*       db = dst + (size_t)b * NTOK * CCH;
    const int tx = threadIdx.x & 31, ty = threadIdx.x >> 5;
    #pragma unroll
    for (int j = 0; j < 8; j++) {
        uint32_t v = *(const uint32_t*)&sb[(size_t)(c0 + ty + 8 * j) * NTOK + n0 + tx * 2];
        __nv_bfloat162 v2 = *(__nv_bfloat162*)&v;
        tile[ty + 8 * j][tx * 2 + 0] = v2.x;
        tile[ty + 8 * j][tx * 2 + 1] = v2.y;
    }
    __syncthreads();
    #pragma unroll
    for (int j = 0; j < 8; j++) {
        int n = ty + 8 * j;
        __nv_bfloat162 v2;
        v2.x = tile[tx * 2 + 0][n];
        v2.y = tile[tx * 2 + 1][n];
        *(uint32_t*)&db[(size_t)(n0 + n) * CCH + c0 + tx * 2] = *(uint32_t*)&v2;
    }
}

// ---------------- fp32 -> bf16 elementwise ----------------------------------
__global__ __launch_bounds__(256)
void f2bf_kernel(const float* __restrict__ src, bf16* __restrict__ dst) {
    size_t i = (size_t)blockIdx.x * blockDim.x + threadIdx.x;
    float4 v = ((const float4*)src)[i];
    __nv_bfloat162 lo = __floats2bfloat162_rn(v.x, v.y);
    __nv_bfloat162 hi = __floats2bfloat162_rn(v.z, v.w);
    ((__nv_bfloat162*)dst)[2 * i + 0] = lo;
    ((__nv_bfloat162*)dst)[2 * i + 1] = hi;
}

// ================= bf16 NT GEMM (convs + proj), 4-stage ring =================
#define TILE_ROW 40
#define STAGE_BYTES (128 * TILE_ROW * 2)   // 10240
#define NSTAGE 4
#define SMEM_TOTAL_GEMM (2 * NSTAGE * STAGE_BYTES)   // 81920

__global__ __launch_bounds__(256, 1)
void mma_gemm(const bf16* __restrict__ A, const bf16* __restrict__ B, void* __restrict__ D,
              size_t aBatch, size_t bBatch, size_t dBatch,
              int astride, int bstride, int dstride, int ksteps, float scale,
              const float* __restrict__ bias, int biasMode,
              const float* __restrict__ resid, int outF32) {
    extern __shared__ __align__(16) char smem[];
    const uint32_t sA = smem_u32(smem);
    const uint32_t sB = sA + NSTAGE * STAGE_BYTES;

    const int t    = threadIdx.x;
    const int lane = t & 31;
    const int wid  = t >> 5;
    const int wm   = wid & 1;
    const int wn   = wid >> 1;
    const int bz   = blockIdx.z;
    const int row0 = blockIdx.y * 128;
    const int col0 = blockIdx.x * 128;

    const bf16* Abase = A + (size_t)bz * aBatch + (size_t)row0 * astride;
    const bf16* Bbase = B + (size_t)bz * bBatch + (size_t)col0 * bstride;

    const int lrow = t >> 2;
    const int lcu  = t & 3;

    float acc[4][4][4];
    #pragma unroll
    for (int i = 0; i < 4; i++)
        #pragma unroll
        for (int j = 0; j < 4; j++)
            #pragma unroll
            for (int r = 0; r < 4; r++) acc[i][j][r] = 0.f;

    #pragma unroll
    for (int s = 0; s < NSTAGE - 1; s++) {
        if (s < ksteps) {
            const int k0 = s * 32;
            const uint32_t st = (uint32_t)s * STAGE_BYTES;
            #pragma unroll
            for (int i = 0; i < 2; i++) {
                int row = lrow + i * 64;
                uint32_t soff = st + (uint32_t)(row * TILE_ROW + lcu * 8) * 2;
                cp_async16(sA + soff, Abase + (size_t)row * astride + k0 + lcu * 8);
                cp_async16(sB + soff, Bbase + (size_t)row * bstride + k0 + lcu * 8);
            }
        }
        CP_COMMIT();
    }

    for (int kt = 0; kt < ksteps; kt++) {
        {
            const int ci = kt + NSTAGE - 1;
            if (ci < ksteps) {
                const int k0 = ci * 32;
                const uint32_t st = (uint32_t)(ci & (NSTAGE - 1)) * STAGE_BYTES;
                #pragma unroll
                for (int i = 0; i < 2; i++) {
                    int row = lrow + i * 64;
                    uint32_t soff = st + (uint32_t)(row * TILE_ROW + lcu * 8) * 2;
                    cp_async16(sA + soff, Abase + (size_t)row * astride + k0 + lcu * 8);
                    cp_async16(sB + soff, Bbase + (size_t)row * bstride + k0 + lcu * 8);
                }
            }
            CP_COMMIT();
            CP_WAIT(NSTAGE - 1);
        }
        __syncthreads();

        const uint32_t aB = sA + (uint32_t)(kt & (NSTAGE - 1)) * STAGE_BYTES;
        const uint32_t bB = sB + (uint32_t)(kt & (NSTAGE - 1)) * STAGE_BYTES;
        #pragma unroll
        for (int ks = 0; ks < 2; ks++) {
            uint32_t afr[4][4], bfr[2][4];
            #pragma unroll
            for (int mf = 0; mf < 4; mf++) {
                uint32_t addr = aB + (uint32_t)((wm * 64 + mf * 16 + (lane & 15)) * (TILE_ROW * 2))
                              + (uint32_t)(ks * 32) + ((uint32_t)(lane >> 4) << 4);
                ldsm4(afr[mf], addr);
            }
            #pragma unroll
            for (int ng = 0; ng < 2; ng++) {
                uint32_t addr = bB + (uint32_t)((wn * 32 + ng * 16 + (lane & 7) + ((lane >> 4) & 1) * 8) * (TILE_ROW * 2))
                              + (uint32_t)(ks * 32) + ((uint32_t)((lane >> 3) & 1) << 4);
                ldsm4(bfr[ng], addr);
            }
            #pragma unroll
            for (int mf = 0; mf < 4; mf++)
                #pragma unroll
                for (int nf = 0; nf < 4; nf++)
                    mma16816(acc[mf][nf], afr[mf], &bfr[nf >> 1][(nf & 1) * 2]);
        }
        __syncthreads();
    }

    const float* residb = resid ? resid + (size_t)bz * dBatch : nullptr;
    #pragma unroll
    for (int mf = 0; mf < 4; mf++) {
        int rbase = row0 + wm * 64 + mf * 16 + (lane >> 2);
        #pragma unroll
        for (int nf = 0; nf < 4; nf++) {
            int c = col0 + wn * 32 + nf * 8 + (lane & 3) * 2;
            #pragma unroll
            for (int h = 0; h < 2; h++) {
                int r = rbase + h * 8;
                float v0 = acc[mf][nf][h * 2 + 0] * scale;
                float v1 = acc[mf][nf][h * 2 + 1] * scale;
                if (biasMode == 1)      { float bv = bias[r]; v0 += bv; v1 += bv; }
                else if (biasMode == 2) { v0 += bias[c]; v1 += bias[c + 1]; }
                size_t idx = (size_t)r * dstride + c;
                if (outF32) {
                    if (residb) { v0 += residb[idx]; v1 += residb[idx + 1]; }
                    float2 f; f.x = v0; f.y = v1;
                    *(float2*)((float*)D + (size_t)bz * dBatch + idx) = f;
                } else {
                    *(__nv_bfloat162*)((bf16*)D + (size_t)bz * dBatch + idx) =
                        __floats2bfloat162_rn(v0, v1);
                }
            }
        }
    }
}

// ================= INT8 NT GEMMs (attention) =================================
// Tile 128x128, K-stage 64 bytes, rows padded to 80 bytes. s8 k32 fragments are
// byte-identical to bf16 k16 fragments -> same ldmatrix addressing.
#define IROW 80
#define ISTAGE_BYTES (128 * IROW)     // 10240 (same ring footprint)

// S GEMM: p8[n][m] = clamp(round(exp(acc*f)*PSCALE)), f = (amq/127)(amk/127)/16
__global__ __launch_bounds__(256, 1)
void mma_s8_qk(const int8_t* __restrict__ A, const int8_t* __restrict__ B,
               int8_t* __restrict__ D, const float* __restrict__ amq,
               const float* __restrict__ amk) {
    extern __shared__ __align__(16) char smem[];
    const uint32_t sA = smem_u32(smem);
    const uint32_t sB = sA + NSTAGE * ISTAGE_BYTES;

    const int t    = threadIdx.x;
    const int lane = t & 31;
    const int wid  = t >> 5;
    const int wm   = wid & 1;
    const int wn   = wid >> 1;
    const int bz   = blockIdx.z;
    const int row0 = blockIdx.y * 128;
    const int col0 = blockIdx.x * 128;
    const int ksteps = CCH / 64;    // 4

    const int8_t* Abase = A + (size_t)bz * NTOK * CCH + (size_t)row0 * CCH;
    const int8_t* Bbase = B + (size_t)bz * NTOK * CCH + (size_t)col0 * CCH;

    const int lrow = t >> 1;            // 0..127 (2 chunks of 16B per row half)
    const int lcu  = t & 1;             // with i loop covers 4 chunks of 16B

    int acc[4][4][4];
    #pragma unroll
    for (int i = 0; i < 4; i++)
        #pragma unroll
        for (int j = 0; j < 4; j++)
            #pragma unroll
            for (int r = 0; r < 4; r++) acc[i][j][r] = 0;

    #pragma unroll
    for (int s = 0; s < NSTAGE - 1; s++) {
        if (s < ksteps) {
            const int k0 = s * 64;
            const uint32_t st = (uint32_t)s * ISTAGE_BYTES;
            #pragma unroll
            for (int i = 0; i < 2; i++) {
                int cu = lcu + i * 2;
                uint32_t soff = st + (uint32_t)(lrow * IROW + cu * 16);
                cp_async16(sA + soff, Abase + (size_t)lrow * CCH + k0 + cu * 16);
                cp_async16(sB + soff, Bbase + (size_t)lrow * CCH + k0 + cu * 16);
            }
        }
        CP_COMMIT();
    }

    for (int kt = 0; kt < ksteps; kt++) {
        {
            const int ci = kt + NSTAGE - 1;
            if (ci < ksteps) {
                const int k0 = ci * 64;
                const uint32_t st = (uint32_t)(ci & (NSTAGE - 1)) * ISTAGE_BYTES;
                #pragma unroll
                for (int i = 0; i < 2; i++) {
                    int cu = lcu + i * 2;
                    uint32_t soff = st + (uint32_t)(lrow * IROW + cu * 16);
                    cp_async16(sA + soff, Abase + (size_t)lrow * CCH + k0 + cu * 16);
                    cp_async16(sB + soff, Bbase + (size_t)lrow * CCH + k0 + cu * 16);
                }
            }
            CP_COMMIT();
            CP_WAIT(NSTAGE - 1);
        }
        __syncthreads();

        const uint32_t aB = sA + (uint32_t)(kt & (NSTAGE - 1)) * ISTAGE_BYTES;
        const uint32_t bB = sB + (uint32_t)(kt & (NSTAGE - 1)) * ISTAGE_BYTES;
        #pragma unroll
        for (int ks = 0; ks < 2; ks++) {       // two k32 steps per 64B stage
            uint32_t afr[4][4], bfr[2][4];
            #pragma unroll
            for (int mf = 0; mf < 4; mf++) {
                uint32_t addr = aB + (uint32_t)((wm * 64 + mf * 16 + (lane & 15)) * IROW)
                              + (uint32_t)(ks * 32) + ((uint32_t)(lane >> 4) << 4);
                ldsm4(afr[mf], addr);
            }
            #pragma unroll
            for (int ng = 0; ng < 2; ng++) {
                uint32_t addr = bB + (uint32_t)((wn * 32 + ng * 16 + (lane & 7) + ((lane >> 4) & 1) * 8) * IROW)
                              + (uint32_t)(ks * 32) + ((uint32_t)((lane >> 3) & 1) << 4);
                ldsm4(bfr[ng], addr);
            }
            #pragma unroll
            for (int mf = 0; mf < 4; mf++)
                #pragma unroll
                for (int nf = 0; nf < 4; nf++)
                    mma16832s8(acc[mf][nf], afr[mf], &bfr[nf >> 1][(nf & 1) * 2]);
        }
        __syncthreads();
    }

    const float f = (amq[0] / 127.f) * (amk[0] / 127.f) * 0.0625f;
    int8_t* Db = D + (size_t)bz * NTOK * NTOK;
    #pragma unroll
    for (int mf = 0; mf < 4; mf++) {
        int rbase = row0 + wm * 64 + mf * 16 + (lane >> 2);
        #pragma unroll
        for (int nf = 0; nf < 4; nf++) {
            int c = col0 + wn * 32 + nf * 8 + (lane & 3) * 2;
            #pragma unroll
            for (int h = 0; h < 2; h++) {
                int r = rbase + h * 8;
                float p0 = __expf((float)acc[mf][nf][h * 2 + 0] * f) * PSCALE;
                float p1 = __expf((float)acc[mf][nf][h * 2 + 1] * f) * PSCALE;
                char2 o;
                o.x = (char)min(127, __float2int_rn(p0));
                o.y = (char)min(127, __float2int_rn(p1));
                *(char2*)&Db[(size_t)r * NTOK + c] = o;
            }
        }
    }
}

// AV GEMM: ht[n][o] = (sum_m p8*v8) / (sum_m p8) * (amv/127), integer row sums.
__global__ __launch_bounds__(256, 1)
void mma_s8_av(const int8_t* __restrict__ A, const int8_t* __restrict__ B,
               bf16* __restrict__ D, const float* __restrict__ amv) {
    extern __shared__ __align__(16) char smem[];
    __shared__ int sumrow[128];
    const uint32_t sA = smem_u32(smem);
    const uint32_t sB = sA + NSTAGE * ISTAGE_BYTES;

    const int t    = threadIdx.x;
    const int lane = t & 31;
    const int wid  = t >> 5;
    const int wm   = wid & 1;
    const int wn   = wid >> 1;
    const int bz   = blockIdx.z;
    const int row0 = blockIdx.y * 128;
    const int col0 = blockIdx.x * 128;
    const int ksteps = NTOK / 64;    // 64

    const int8_t* Abase = A + (size_t)bz * NTOK * NTOK + (size_t)row0 * NTOK;
    const int8_t* Bbase = B + (size_t)bz * CCH * NTOK + (size_t)col0 * NTOK;

    const int lrow = t >> 1;
    const int lcu  = t & 1;

    int acc[4][4][4];
    #pragma unroll
    for (int i = 0; i < 4; i++)
        #pragma unroll
        for (int j = 0; j < 4; j++)
            #pragma unroll
            for (int r = 0; r < 4; r++) acc[i][j][r] = 0;
    int rs = 0;
    const int srow = t >> 1;            // 2 threads per row, 32 bytes each
    const int skoff = (t & 1) * 32;

    #pragma unroll
    for (int s = 0; s < NSTAGE - 1; s++) {
        const int k0 = s * 64;
        const uint32_t st = (uint32_t)s * ISTAGE_BYTES;
        #pragma unroll
        for (int i = 0; i < 2; i++) {
            int cu = lcu + i * 2;
            uint32_t soff = st + (uint32_t)(lrow * IROW + cu * 16);
            cp_async16(sA + soff, Abase + (size_t)lrow * NTOK + k0 + cu * 16);
            cp_async16(sB + soff, Bbase + (size_t)lrow * NTOK + k0 + cu * 16);
        }
        CP_COMMIT();
    }

    for (int kt = 0; kt < ksteps; kt++) {
        {
            const int ci = kt + NSTAGE - 1;
            if (ci < ksteps) {
                const int k0 = ci * 64;
                const uint32_t st = (uint32_t)(ci & (NSTAGE - 1)) * ISTAGE_BYTES;
                #pragma unroll
                for (int i = 0; i < 2; i++) {
                    int cu = lcu + i * 2;
                    uint32_t soff = st + (uint32_t)(lrow * IROW + cu * 16);
                    cp_async16(sA + soff, Abase + (size_t)lrow * NTOK + k0 + cu * 16);
                    cp_async16(sB + soff, Bbase + (size_t)lrow * NTOK + k0 + cu * 16);
                }
            }
            CP_COMMIT();
            CP_WAIT(NSTAGE - 1);
        }
        __syncthreads();

        const uint32_t aB = sA + (uint32_t)(kt & (NSTAGE - 1)) * ISTAGE_BYTES;
        const uint32_t bB = sB + (uint32_t)(kt & (NSTAGE - 1)) * ISTAGE_BYTES;
        #pragma unroll
        for (int ks = 0; ks < 2; ks++) {
            uint32_t afr[4][4], bfr[2][4];
            #pragma unroll
            for (int mf = 0; mf < 4; mf++) {
                uint32_t addr = aB + (uint32_t)((wm * 64 + mf * 16 + (lane & 15)) * IROW)
                              + (uint32_t)(ks * 32) + ((uint32_t)(lane >> 4) << 4);
                ldsm4(afr[mf], addr);
            }
            #pragma unroll
            for (int ng = 0; ng < 2; ng++) {
                uint32_t addr = bB + (uint32_t)((wn * 32 + ng * 16 + (lane & 7) + ((lane >> 4) & 1) * 8) * IROW)
                              + (uint32_t)(ks * 32) + ((uint32_t)((lane >> 3) & 1) << 4);
                ldsm4(bfr[ng], addr);
            }
            #pragma unroll
            for (int mf = 0; mf < 4; mf++)
                #pragma unroll
                for (int nf = 0; nf < 4; nf++)
                    mma16832s8(acc[mf][nf], afr[mf], &bfr[nf >> 1][(nf & 1) * 2]);
        }

        // integer row-sum of this p8 stage (exact, order-independent)
        {
            const char* base = smem + (size_t)(kt & (NSTAGE - 1)) * ISTAGE_BYTES
                             + srow * IROW + skoff;
            int4 w0 = *(const int4*)(base);
            int4 w1 = *(const int4*)(base + 16);
            const int ones = 0x01010101;
            rs = __dp4a(w0.x, ones, rs); rs = __dp4a(w0.y, ones, rs);
            rs = __dp4a(w0.z, ones, rs); rs = __dp4a(w0.w, ones, rs);
            rs = __dp4a(w1.x, ones, rs); rs = __dp4a(w1.y, ones, rs);
            rs = __dp4a(w1.z, ones, rs); rs = __dp4a(w1.w, ones, rs);
        }
        __syncthreads();
    }

    rs += __shfl_xor_sync(0xffffffffu, rs, 1);
    if ((t & 1) == 0) sumrow[srow] = rs;
    __syncthreads();

    const float vscale = amv[0] / 127.f;
    bf16* Db = D + (size_t)bz * NTOK * CCH;
    #pragma unroll
    for (int mf = 0; mf < 4; mf++) {
        int rloc = wm * 64 + mf * 16 + (lane >> 2);
        #pragma unroll
        for (int nf = 0; nf < 4; nf++) {
            int c = col0 + wn * 32 + nf * 8 + (lane & 3) * 2;
            #pragma unroll
            for (int h = 0; h < 2; h++) {
                int rl = rloc + h * 8;
                float inv = vscale / (float)sumrow[rl];
                float v0 = (float)acc[mf][nf][h * 2 + 0] * inv;
                float v1 = (float)acc[mf][nf][h * 2 + 1] * inv;
                *(__nv_bfloat162*)&Db[(size_t)(row0 + rl) * CCH + c] =
                    __floats2bfloat162_rn(v0, v1);
            }
        }
    }
}

// ---------------- launch ------------------------------------------------------
extern "C" void kernel_launch(void* const* d_in, const int* in_sizes, int n_in,
                              void* d_out, int out_size) {
    const float* x     = (const float*)d_in[0];
    const float* gns   = (const float*)d_in[1];
    const float* gnb   = (const float*)d_in[2];
    const float* wq    = (const float*)d_in[3];
    const float* bq    = (const float*)d_in[4];
    const float* wk    = (const float*)d_in[5];
    const float* bk    = (const float*)d_in[6];
    const float* wv    = (const float*)d_in[7];
    const float* bv    = (const float*)d_in[8];
    const float* wproj = (const float*)d_in[9];
    const float* bproj = (const float*)d_in[10];
    float* out = (float*)d_out;

    bf16 *hnb, *hnT, *qt, *kt, *vb, *ht, *wqb, *wkb, *wvb, *wpb;
    int8_t *q8, *k8, *v8, *p8;
    float* am;
    cudaGetSymbolAddress((void**)&hnb, g_hnb);
    cudaGetSymbolAddress((void**)&hnT, g_hnT);
    cudaGetSymbolAddress((void**)&qt,  g_qt);
    cudaGetSymbolAddress((void**)&kt,  g_kt);
    cudaGetSymbolAddress((void**)&vb,  g_vb);
    cudaGetSymbolAddress((void**)&ht,  g_ht);
    cudaGetSymbolAddress((void**)&q8,  g_q8);
    cudaGetSymbolAddress((void**)&k8,  g_k8);
    cudaGetSymbolAddress((void**)&v8,  g_v8);
    cudaGetSymbolAddress((void**)&p8,  g_p8);
    cudaGetSymbolAddress((void**)&wqb, g_wqb);
    cudaGetSymbolAddress((void**)&wkb, g_wkb);
    cudaGetSymbolAddress((void**)&wvb, g_wvb);
    cudaGetSymbolAddress((void**)&wpb, g_wpb);
    cudaGetSymbolAddress((void**)&am,  g_absmax);

    cudaFuncSetAttribute(mma_gemm,  cudaFuncAttributeMaxDynamicSharedMemorySize, SMEM_TOTAL_GEMM);
    cudaFuncSetAttribute(mma_s8_qk, cudaFuncAttributeMaxDynamicSharedMemorySize, SMEM_TOTAL_GEMM);
    cudaFuncSetAttribute(mma_s8_av, cudaFuncAttributeMaxDynamicSharedMemorySize, SMEM_TOTAL_GEMM);

    const size_t CN = (size_t)CCH * NTOK;      // 1,048,576

    init_scales_kernel<<<1, 32>>>();

    // 1. GroupNorm -> bf16
    gn_kernel<<<BBATCH * NG, 256>>>(x, gns, gnb);

    // 2. transpose -> hnT [n][c]
    dim3 gt(NTOK / 64, CCH / 64, BBATCH);
    transpose_kernel<<<gt, 256>>>(hnb, hnT);

    // 3. weights -> bf16
    f2bf_kernel<<<64, 256>>>(wq,    wqb);
    f2bf_kernel<<<64, 256>>>(wk,    wkb);
    f2bf_kernel<<<64, 256>>>(wv,    wvb);
    f2bf_kernel<<<64, 256>>>(wproj, wpb);

    // 4. convs (bf16)
    dim3 gq(CCH / 128, NTOK / 128, BBATCH);
    mma_gemm<<<gq, 256, SMEM_TOTAL_GEMM>>>(hnT, wqb, qt, CN, 0, CN, CCH, CCH, CCH, CCH / 32, 1.f, bq, 2, nullptr, 0);
    mma_gemm<<<gq, 256, SMEM_TOTAL_GEMM>>>(hnT, wkb, kt, CN, 0, CN, CCH, CCH, CCH, CCH / 32, 1.f, bk, 2, nullptr, 0);
    dim3 gv(NTOK / 128, CCH / 128, BBATCH);
    mma_gemm<<<gv, 256, SMEM_TOTAL_GEMM>>>(wvb, hnT, vb, 0, CN, CN, CCH, CCH, NTOK, CCH / 32, 1.f, bv, 1, nullptr, 0);

    // 5. dynamic absmax + quantize to int8
    const size_t n2 = (size_t)BBATCH * CN / 2;
    absmax_kernel<<<1024, 256>>>(qt, n2, am + 0);
    absmax_kernel<<<1024, 256>>>(kt, n2, am + 1);
    absmax_kernel<<<1024, 256>>>(vb, n2, am + 2);
    const unsigned qgrid = (unsigned)((size_t)BBATCH * CN / 4 / 256);
    quant_kernel<<<qgrid, 256>>>(qt, q8, am + 0);
    quant_kernel<<<qgrid, 256>>>(kt, k8, am + 1);
    quant_kernel<<<qgrid, 256>>>(vb, v8, am + 2);

    // 6. int8 S GEMM with fused exp -> p8
    dim3 gs(NTOK / 128, NTOK / 128, BBATCH);
    mma_s8_qk<<<gs, 256, SMEM_TOTAL_GEMM>>>(q8, k8, p8, am + 0, am + 1);

    // 7. int8 AV GEMM with integer row-sum normalization -> ht bf16
    dim3 gh(CCH / 128, NTOK / 128, BBATCH);
    mma_s8_av<<<gh, 256, SMEM_TOTAL_GEMM>>>(p8, v8, ht, am + 2);

    // 8. proj + bias + residual -> out (bf16 GEMM, fp32 out)
    dim3 go(NTOK / 128, CCH / 128, BBATCH);
    mma_gemm<<<go, 256, SMEM_TOTAL_GEMM>>>(wpb, ht, out, 0, CN, CN, CCH, CCH, NTOK, CCH / 32, 1.f,
                          bproj, 1, x, 1);
}

// round 11
// speedup vs baseline: 1.8499x; 1.8499x over previous
#include <cuda_runtime.h>
#include <cuda_bf16.h>
#include <cstddef>
#include <cstdint>

#define BBATCH 8
#define CCH    256
#define NTOK   4096     // 64*64
#define NG     32
#define CPG    8
#define EPSV   1e-6f

typedef __nv_bfloat16 bf16;

// ---------------- scratch (device globals; no allocation allowed) ----------
__device__ bf16  g_hnb[(size_t)BBATCH * CCH * NTOK];   // GN out [c][n]
__device__ bf16  g_hnT[(size_t)BBATCH * NTOK * CCH];   // GN out transposed [n][c]
__device__ bf16  g_qt [(size_t)BBATCH * NTOK * CCH];   // Q^T [n][o]
__device__ bf16  g_kt [(size_t)BBATCH * NTOK * CCH];   // K^T [m][o]
__device__ bf16  g_vb [(size_t)BBATCH * CCH * NTOK];   // V [o][m]
__device__ bf16  g_ht [(size_t)BBATCH * NTOK * CCH];   // attn out^T [n][o]
__device__ bf16  g_p  [(size_t)BBATCH * NTOK * NTOK];  // bf16 exp(S) (unnormalized)
__device__ bf16  g_wqb[CCH * CCH];
__device__ bf16  g_wkb[CCH * CCH];
__device__ bf16  g_wvb[CCH * CCH];
__device__ bf16  g_wpb[CCH * CCH];

// ================= low-level helpers ========================================
__device__ __forceinline__ uint32_t smem_u32(const void* p) {
    uint32_t a;
    asm("{ .reg .u64 t; cvta.to.shared.u64 t, %1; cvt.u32.u64 %0, t; }" : "=r"(a) : "l"(p));
    return a;
}
__device__ __forceinline__ void cp_async16(uint32_t saddr, const void* gaddr) {
    asm volatile("cp.async.cg.shared.global [%0], [%1], 16;" :: "r"(saddr), "l"(gaddr));
}
#define CP_COMMIT() asm volatile("cp.async.commit_group;" ::: "memory")
#define CP_WAIT(n)  asm volatile("cp.async.wait_group %0;" :: "n"(n) : "memory")

__device__ __forceinline__ void ldsm4(uint32_t* r, uint32_t addr) {
    asm volatile("ldmatrix.sync.aligned.m8n8.x4.shared.b16 {%0,%1,%2,%3}, [%4];"
                 : "=r"(r[0]), "=r"(r[1]), "=r"(r[2]), "=r"(r[3]) : "r"(addr));
}
__device__ __forceinline__ void mma16816(float* c, const uint32_t* a, const uint32_t* b) {
    asm volatile("mma.sync.aligned.m16n8k16.row.col.f32.bf16.bf16.f32 "
                 "{%0,%1,%2,%3}, {%4,%5,%6,%7}, {%8,%9}, {%0,%1,%2,%3};"
                 : "+f"(c[0]), "+f"(c[1]), "+f"(c[2]), "+f"(c[3])
                 : "r"(a[0]), "r"(a[1]), "r"(a[2]), "r"(a[3]),
                   "r"(b[0]), "r"(b[1]));
}

// ---------------- block reductions (blockDim == 256) -----------------------
__device__ __forceinline__ float blk_reduce_sum(float v, float* sh) {
    int lane = threadIdx.x & 31, w = threadIdx.x >> 5;
    #pragma unroll
    for (int o = 16; o; o >>= 1) v += __shfl_xor_sync(0xffffffffu, v, o);
    __syncthreads();
    if (lane == 0) sh[w] = v;
    __syncthreads();
    if (threadIdx.x == 0) {
        float r = 0.f;
        #pragma unroll
        for (int i = 0; i < 8; i++) r += sh[i];
        sh[0] = r;
    }
    __syncthreads();
    return sh[0];
}

// ---------------- GroupNorm (bf16 out) --------------------------------------
__global__ __launch_bounds__(256)
void gn_kernel(const float* __restrict__ x, const float* __restrict__ gsc,
               const float* __restrict__ gbi) {
    __shared__ float sh[8];
    int b = blockIdx.x >> 5;
    int g = blockIdx.x & 31;
    const size_t base = ((size_t)b * CCH + (size_t)g * CPG) * NTOK;
    const float* xp = x + base;
    const int total = CPG * NTOK;
    float s = 0.f, ss = 0.f;
    for (int i = threadIdx.x; i < total; i += 256) {
        float v = xp[i];
        s += v; ss += v * v;
    }
    s  = blk_reduce_sum(s,  sh);
    ss = blk_reduce_sum(ss, sh);
    const float inv_n = 1.f / (float)total;
    float mean = s * inv_n;
    float var  = ss * inv_n - mean * mean;
    float rstd = rsqrtf(var + EPSV);
    for (int i = threadIdx.x; i < total; i += 256) {
        int c = g * CPG + (i >> 12);
        g_hnb[base + i] = __float2bfloat16((xp[i] - mean) * rstd * gsc[c] + gbi[c]);
    }
}

// ---------------- bf16 transpose [C][N] -> [N][C] ----------------------------
__global__ __launch_bounds__(256)
void transpose_kernel(const bf16* __restrict__ src, bf16* __restrict__ dst) {
    __shared__ bf16 tile[64][65];
    const int b  = blockIdx.z;
    const int n0 = blockIdx.x * 64;
    const int c0 = blockIdx.y * 64;
    const bf16* sb = src + (size_t)b * CCH * NTOK;
    bf16*       db = dst + (size_t)b * NTOK * CCH;
    const int tx = threadIdx.x & 31, ty = threadIdx.x >> 5;
    #pragma unroll
    for (int j = 0; j < 8; j++) {
        uint32_t v = *(const uint32_t*)&sb[(size_t)(c0 + ty + 8 * j) * NTOK + n0 + tx * 2];
        __nv_bfloat162 v2 = *(__nv_bfloat162*)&v;
        tile[ty + 8 * j][tx * 2 + 0] = v2.x;
        tile[ty + 8 * j][tx * 2 + 1] = v2.y;
    }
    __syncthreads();
    #pragma unroll
    for (int j = 0; j < 8; j++) {
        int n = ty + 8 * j;
        __nv_bfloat162 v2;
        v2.x = tile[tx * 2 + 0][n];
        v2.y = tile[tx * 2 + 1][n];
        *(uint32_t*)&db[(size_t)(n0 + n) * CCH + c0 + tx * 2] = *(uint32_t*)&v2;
    }
}

// ---------------- fp32 -> bf16 elementwise ----------------------------------
__global__ __launch_bounds__(256)
void f2bf_kernel(const float* __restrict__ src, bf16* __restrict__ dst) {
    size_t i = (size_t)blockIdx.x * blockDim.x + threadIdx.x;   // float4 index
    float4 v = ((const float4*)src)[i];
    __nv_bfloat162 lo = __floats2bfloat162_rn(v.x, v.y);
    __nv_bfloat162 hi = __floats2bfloat162_rn(v.z, v.w);
    ((__nv_bfloat162*)dst)[2 * i + 0] = lo;
    ((__nv_bfloat162*)dst)[2 * i + 1] = hi;
}

// ---------------- NT bf16 GEMM: D[r][c] = scale*sum_k A[r][k]B[c][k] + ... ---
// Block tile 128(M) x 128(N) x 32(K). 256 thr = 8 warps (2 M x 4 N).
// Warp tile 64x32: 4 m-frags (16) x 4 n-frags (8). cp.async 4-stage ring.
// __launch_bounds__(256, 2): 2 CTAs/SM to hide barrier/pipeline latency.
#define TILE_ROW 40   // padded row elems (80 B) -> conflict-free ldmatrix
#define STAGE_BYTES (128 * TILE_ROW * 2)   // 10240
#define NSTAGE 4
#define SMEM_TOTAL_GEMM (2 * NSTAGE * STAGE_BYTES)   // 81920

__global__ __launch_bounds__(256, 2)
void mma_gemm(const bf16* __restrict__ A, const bf16* __restrict__ B, void* __restrict__ D,
              size_t aBatch, size_t bBatch, size_t dBatch,
              int astride, int bstride, int dstride, int ksteps, float scale,
              const float* __restrict__ bias, int biasMode,
              const float* __restrict__ resid, int outF32, int expOut) {
    extern __shared__ __align__(16) char smem[];
    const uint32_t sA = smem_u32(smem);
    const uint32_t sB = sA + NSTAGE * STAGE_BYTES;

    const int t    = threadIdx.x;
    const int lane = t & 31;
    const int wid  = t >> 5;
    const int wm   = wid & 1;
    const int wn   = wid >> 1;
    const int bz   = blockIdx.z;
    const int row0 = blockIdx.y * 128;
    const int col0 = blockIdx.x * 128;

    const bf16* Abase = A + (size_t)bz * aBatch + (size_t)row0 * astride;
    const bf16* Bbase = B + (size_t)bz * bBatch + (size_t)col0 * bstride;

    const int lrow = t >> 2;
    const int lcu  = t & 3;

    float acc[4][4][4];
    #pragma unroll
    for (int i = 0; i < 4; i++)
        #pragma unroll
        for (int j = 0; j < 4; j++)
            #pragma unroll
            for (int r = 0; r < 4; r++) acc[i][j][r] = 0.f;

    // prologue: chunks 0..NSTAGE-2, one commit-group each
    #pragma unroll
    for (int s = 0; s < NSTAGE - 1; s++) {
        if (s < ksteps) {
            const int k0 = s * 32;
            const uint32_t st = (uint32_t)s * STAGE_BYTES;
            #pragma unroll
            for (int i = 0; i < 2; i++) {
                int row = lrow + i * 64;
                uint32_t soff = st + (uint32_t)(row * TILE_ROW + lcu * 8) * 2;
                cp_async16(sA + soff, Abase + (size_t)row * astride + k0 + lcu * 8);
                cp_async16(sB + soff, Bbase + (size_t)row * bstride + k0 + lcu * 8);
            }
        }
        CP_COMMIT();
    }

    for (int kt = 0; kt < ksteps; kt++) {
        {
            const int ci = kt + NSTAGE - 1;
            if (ci < ksteps) {
                const int k0 = ci * 32;
                const uint32_t st = (uint32_t)(ci & (NSTAGE - 1)) * STAGE_BYTES;
                #pragma unroll
                for (int i = 0; i < 2; i++) {
                    int row = lrow + i * 64;
                    uint32_t soff = st + (uint32_t)(row * TILE_ROW + lcu * 8) * 2;
                    cp_async16(sA + soff, Abase + (size_t)row * astride + k0 + lcu * 8);
                    cp_async16(sB + soff, Bbase + (size_t)row * bstride + k0 + lcu * 8);
                }
            }
            CP_COMMIT();           // always commit (empty group in tail)
            CP_WAIT(NSTAGE - 1);   // chunk kt complete
        }
        __syncthreads();

        const uint32_t aB = sA + (uint32_t)(kt & (NSTAGE - 1)) * STAGE_BYTES;
        const uint32_t bB = sB + (uint32_t)(kt & (NSTAGE - 1)) * STAGE_BYTES;
        #pragma unroll
        for (int ks = 0; ks < 2; ks++) {
            uint32_t afr[4][4], bfr[2][4];
            #pragma unroll
            for (int mf = 0; mf < 4; mf++) {
                uint32_t addr = aB + (uint32_t)((wm * 64 + mf * 16 + (lane & 15)) * (TILE_ROW * 2))
                              + (uint32_t)(ks * 32) + ((uint32_t)(lane >> 4) << 4);
                ldsm4(afr[mf], addr);
            }
            #pragma unroll
            for (int ng = 0; ng < 2; ng++) {
                uint32_t addr = bB + (uint32_t)((wn * 32 + ng * 16 + (lane & 7) + ((lane >> 4) & 1) * 8) * (TILE_ROW * 2))
                              + (uint32_t)(ks * 32) + ((uint32_t)((lane >> 3) & 1) << 4);
                ldsm4(bfr[ng], addr);
            }
            #pragma unroll
            for (int mf = 0; mf < 4; mf++)
                #pragma unroll
                for (int nf = 0; nf < 4; nf++)
                    mma16816(acc[mf][nf], afr[mf], &bfr[nf >> 1][(nf & 1) * 2]);
        }
        __syncthreads();
    }

    // epilogue
    const float* residb = resid ? resid + (size_t)bz * dBatch : nullptr;
    #pragma unroll
    for (int mf = 0; mf < 4; mf++) {
        int rbase = row0 + wm * 64 + mf * 16 + (lane >> 2);
        #pragma unroll
        for (int nf = 0; nf < 4; nf++) {
            int c = col0 + wn * 32 + nf * 8 + (lane & 3) * 2;
            #pragma unroll
            for (int h = 0; h < 2; h++) {
                int r = rbase + h * 8;
                float v0 = acc[mf][nf][h * 2 + 0] * scale;
                float v1 = acc[mf][nf][h * 2 + 1] * scale;
                if (biasMode == 1)      { float bv = bias[r]; v0 += bv; v1 += bv; }
                else if (biasMode == 2) { v0 += bias[c]; v1 += bias[c + 1]; }
                size_t idx = (size_t)r * dstride + c;
                if (outF32) {
                    if (residb) { v0 += residb[idx]; v1 += residb[idx + 1]; }
                    float2 f; f.x = v0; f.y = v1;
                    *(float2*)((float*)D + (size_t)bz * dBatch + idx) = f;
                } else {
                    if (expOut) { v0 = __expf(v0); v1 = __expf(v1); }
                    *(__nv_bfloat162*)((bf16*)D + (size_t)bz * dBatch + idx) =
                        __floats2bfloat162_rn(v0, v1);
                }
            }
        }
    }
}

// ---------------- AV GEMM with inline row-sum normalization ------------------
// ht[n][o] = (1/rowsum_n) * sum_m expS[n][m] * vb[o][m]
__global__ __launch_bounds__(256, 2)
void mma_av(const bf16* __restrict__ A, const bf16* __restrict__ B, bf16* __restrict__ D) {
    extern __shared__ __align__(16) char smem[];
    __shared__ float sumrow[128];
    const uint32_t sA = smem_u32(smem);
    const uint32_t sB = sA + NSTAGE * STAGE_BYTES;

    const int t    = threadIdx.x;
    const int lane = t & 31;
    const int wid  = t >> 5;
    const int wm   = wid & 1;
    const int wn   = wid >> 1;
    const int bz   = blockIdx.z;
    const int row0 = blockIdx.y * 128;
    const int col0 = blockIdx.x * 128;

    const bf16* Abase = A + (size_t)bz * NTOK * NTOK + (size_t)row0 * NTOK;
    const bf16* Bbase = B + (size_t)bz * CCH * NTOK + (size_t)col0 * NTOK;

    const int lrow = t >> 2;
    const int lcu  = t & 3;
    const int ksteps = NTOK / 32;   // 128

    float acc[4][4][4];
    #pragma unroll
    for (int i = 0; i < 4; i++)
        #pragma unroll
        for (int j = 0; j < 4; j++)
            #pragma unroll
            for (int r = 0; r < 4; r++) acc[i][j][r] = 0.f;
    float rs = 0.f;
    const int srow = t >> 1;            // 2 threads per A row for the row sum
    const int skoff = (t & 1) * 16;

    #pragma unroll
    for (int s = 0; s < NSTAGE - 1; s++) {
        const int k0 = s * 32;
        const uint32_t st = (uint32_t)s * STAGE_BYTES;
        #pragma unroll
        for (int i = 0; i < 2; i++) {
            int row = lrow + i * 64;
            uint32_t soff = st + (uint32_t)(row * TILE_ROW + lcu * 8) * 2;
            cp_async16(sA + soff, Abase + (size_t)row * NTOK + k0 + lcu * 8);
            cp_async16(sB + soff, Bbase + (size_t)row * NTOK + k0 + lcu * 8);
        }
        CP_COMMIT();
    }

    for (int kt = 0; kt < ksteps; kt++) {
        {
            const int ci = kt + NSTAGE - 1;
            if (ci < ksteps) {
                const int k0 = ci * 32;
                const uint32_t st = (uint32_t)(ci & (NSTAGE - 1)) * STAGE_BYTES;
                #pragma unroll
                for (int i = 0; i < 2; i++) {
                    int row = lrow + i * 64;
                    uint32_t soff = st + (uint32_t)(row * TILE_ROW + lcu * 8) * 2;
                    cp_async16(sA + soff, Abase + (size_t)row * NTOK + k0 + lcu * 8);
                    cp_async16(sB + soff, Bbase + (size_t)row * NTOK + k0 + lcu * 8);
                }
            }
            CP_COMMIT();
            CP_WAIT(NSTAGE - 1);
        }
        __syncthreads();

        const uint32_t aB = sA + (uint32_t)(kt & (NSTAGE - 1)) * STAGE_BYTES;
        const uint32_t bB = sB + (uint32_t)(kt & (NSTAGE - 1)) * STAGE_BYTES;
        #pragma unroll
        for (int ks = 0; ks < 2; ks++) {
            uint32_t afr[4][4], bfr[2][4];
            #pragma unroll
            for (int mf = 0; mf < 4; mf++) {
                uint32_t addr = aB + (uint32_t)((wm * 64 + mf * 16 + (lane & 15)) * (TILE_ROW * 2))
                              + (uint32_t)(ks * 32) + ((uint32_t)(lane >> 4) << 4);
                ldsm4(afr[mf], addr);
            }
            #pragma unroll
            for (int ng = 0; ng < 2; ng++) {
                uint32_t addr = bB + (uint32_t)((wn * 32 + ng * 16 + (lane & 7) + ((lane >> 4) & 1) * 8) * (TILE_ROW * 2))
                              + (uint32_t)(ks * 32) + ((uint32_t)((lane >> 3) & 1) << 4);
                ldsm4(bfr[ng], addr);
            }
            #pragma unroll
            for (int mf = 0; mf < 4; mf++)
                #pragma unroll
                for (int nf = 0; nf < 4; nf++)
                    mma16816(acc[mf][nf], afr[mf], &bfr[nf >> 1][(nf & 1) * 2]);
        }

        // inline row-sum of this A (expS) stage: deterministic per-thread order
        {
            const bf16* arow = (const bf16*)(smem
                + (size_t)(kt & (NSTAGE - 1)) * STAGE_BYTES)
                + srow * TILE_ROW + skoff;
            float part = 0.f;
            #pragma unroll
            for (int j = 0; j < 8; j++) {
                __nv_bfloat162 u = *(const __nv_bfloat162*)&arow[2 * j];
                part += __bfloat162float(u.x) + __bfloat162float(u.y);
            }
            rs += part;
        }
        __syncthreads();
    }

    // combine row-sum halves (lanes t, t^1 adjacent in same warp)
    rs += __shfl_xor_sync(0xffffffffu, rs, 1);
    if ((t & 1) == 0) sumrow[srow] = rs;
    __syncthreads();

    // epilogue: normalize rows, write bf16
    bf16* Db = D + (size_t)bz * NTOK * CCH;
    #pragma unroll
    for (int mf = 0; mf < 4; mf++) {
        int rloc = wm * 64 + mf * 16 + (lane >> 2);
        #pragma unroll
        for (int nf = 0; nf < 4; nf++) {
            int c = col0 + wn * 32 + nf * 8 + (lane & 3) * 2;
            #pragma unroll
            for (int h = 0; h < 2; h++) {
                int rl = rloc + h * 8;
                float inv = 1.f / sumrow[rl];
                float v0 = acc[mf][nf][h * 2 + 0] * inv;
                float v1 = acc[mf][nf][h * 2 + 1] * inv;
                *(__nv_bfloat162*)&Db[(size_t)(row0 + rl) * CCH + c] =
                    __floats2bfloat162_rn(v0, v1);
            }
        }
    }
}

// ---------------- launch ------------------------------------------------------
extern "C" void kernel_launch(void* const* d_in, const int* in_sizes, int n_in,
                              void* d_out, int out_size) {
    const float* x     = (const float*)d_in[0];
    const float* gns   = (const float*)d_in[1];
    const float* gnb   = (const float*)d_in[2];
    const float* wq    = (const float*)d_in[3];
    const float* bq    = (const float*)d_in[4];
    const float* wk    = (const float*)d_in[5];
    const float* bk    = (const float*)d_in[6];
    const float* wv    = (const float*)d_in[7];
    const float* bv    = (const float*)d_in[8];
    const float* wproj = (const float*)d_in[9];
    const float* bproj = (const float*)d_in[10];
    float* out = (float*)d_out;

    bf16 *hnb, *hnT, *qt, *kt, *vb, *ht, *p, *wqb, *wkb, *wvb, *wpb;
    cudaGetSymbolAddress((void**)&hnb, g_hnb);
    cudaGetSymbolAddress((void**)&hnT, g_hnT);
    cudaGetSymbolAddress((void**)&qt,  g_qt);
    cudaGetSymbolAddress((void**)&kt,  g_kt);
    cudaGetSymbolAddress((void**)&vb,  g_vb);
    cudaGetSymbolAddress((void**)&ht,  g_ht);
    cudaGetSymbolAddress((void**)&p,   g_p);
    cudaGetSymbolAddress((void**)&wqb, g_wqb);
    cudaGetSymbolAddress((void**)&wkb, g_wkb);
    cudaGetSymbolAddress((void**)&wvb, g_wvb);
    cudaGetSymbolAddress((void**)&wpb, g_wpb);

    cudaFuncSetAttribute(mma_gemm, cudaFuncAttributeMaxDynamicSharedMemorySize, SMEM_TOTAL_GEMM);
    cudaFuncSetAttribute(mma_av,   cudaFuncAttributeMaxDynamicSharedMemorySize, SMEM_TOTAL_GEMM);

    const size_t CN = (size_t)CCH * NTOK;
    const size_t NN = (size_t)NTOK * NTOK;

    // 1. GroupNorm -> bf16 [c][n]
    gn_kernel<<<BBATCH * NG, 256>>>(x, gns, gnb);

    // 2. transpose -> hnT [n][c]
    dim3 gt(NTOK / 64, CCH / 64, BBATCH);
    transpose_kernel<<<gt, 256>>>(hnb, hnT);

    // 3. weights -> bf16
    f2bf_kernel<<<64, 256>>>(wq,    wqb);
    f2bf_kernel<<<64, 256>>>(wk,    wkb);
    f2bf_kernel<<<64, 256>>>(wv,    wvb);
    f2bf_kernel<<<64, 256>>>(wproj, wpb);

    // 4. qt[n][o] = hnT . Wq^T + bq   (bias per-col)
    dim3 gq(CCH / 128, NTOK / 128, BBATCH);
    mma_gemm<<<gq, 256, SMEM_TOTAL_GEMM>>>(hnT, wqb, qt, CN, 0, CN, CCH, CCH, CCH, CCH / 32, 1.f, bq, 2, nullptr, 0, 0);
    mma_gemm<<<gq, 256, SMEM_TOTAL_GEMM>>>(hnT, wkb, kt, CN, 0, CN, CCH, CCH, CCH, CCH / 32, 1.f, bk, 2, nullptr, 0, 0);

    // 5. vb[o][m] = Wv . hnT^T + bv   (bias per-row)
    dim3 gv(NTOK / 128, CCH / 128, BBATCH);
    mma_gemm<<<gv, 256, SMEM_TOTAL_GEMM>>>(wvb, hnT, vb, 0, CN, CN, CCH, CCH, NTOK, CCH / 32, 1.f, bv, 1, nullptr, 0, 0);

    // 6. expS[n][m] = exp((1/16) qt . kt^T)  -> bf16
    dim3 gs(NTOK / 128, NTOK / 128, BBATCH);
    mma_gemm<<<gs, 256, SMEM_TOTAL_GEMM>>>(qt, kt, p, CN, CN, NN, CCH, CCH, NTOK, CCH / 32, 0.0625f,
                          nullptr, 0, nullptr, 0, 1);

    // 7. ht[n][o] = softmax-normalized expS . vb^T  (row sums inline)
    dim3 gh(CCH / 128, NTOK / 128, BBATCH);
    mma_av<<<gh, 256, SMEM_TOTAL_GEMM>>>(p, vb, ht);

    // 8. out[o][n] = Wproj . ht^T + bproj + x   (fp32 out + residual)
    dim3 go(NTOK / 128, CCH / 128, BBATCH);
    mma_gemm<<<go, 256, SMEM_TOTAL_GEMM>>>(wpb, ht, out, 0, CN, CN, CCH, CCH, NTOK, CCH / 32, 1.f,
                          bproj, 1, x, 1, 0);
}

// round 12
// speedup vs baseline: 1.9825x; 1.0717x over previous
#include <cuda_runtime.h>
#include <cuda_bf16.h>
#include <cstddef>
#include <cstdint>

#define BBATCH 8
#define CCH    256
#define NTOK   4096     // 64*64
#define NG     32
#define CPG    8
#define EPSV   1e-6f

typedef __nv_bfloat16 bf16;

// ---------------- scratch (device globals; no allocation allowed) ----------
__device__ bf16  g_hnb[(size_t)BBATCH * CCH * NTOK];   // GN out [c][n]
__device__ bf16  g_hnT[(size_t)BBATCH * NTOK * CCH];   // GN out transposed [n][c]
__device__ bf16  g_qt [(size_t)BBATCH * NTOK * CCH];   // Q^T [n][o]
__device__ bf16  g_kt [(size_t)BBATCH * NTOK * CCH];   // K^T [m][o]
__device__ bf16  g_vb [(size_t)BBATCH * CCH * NTOK];   // V [o][m]
__device__ bf16  g_ht [(size_t)BBATCH * NTOK * CCH];   // attn out^T [n][o]
__device__ bf16  g_p  [(size_t)BBATCH * NTOK * NTOK];  // bf16 exp(S) (unnormalized)
__device__ bf16  g_wqb[CCH * CCH];
__device__ bf16  g_wkb[CCH * CCH];
__device__ bf16  g_wvb[CCH * CCH];
__device__ bf16  g_wpb[CCH * CCH];

// ================= low-level helpers ========================================
__device__ __forceinline__ uint32_t smem_u32(const void* p) {
    uint32_t a;
    asm("{ .reg .u64 t; cvta.to.shared.u64 t, %1; cvt.u32.u64 %0, t; }" : "=r"(a) : "l"(p));
    return a;
}
__device__ __forceinline__ void cp_async16(uint32_t saddr, const void* gaddr) {
    asm volatile("cp.async.cg.shared.global [%0], [%1], 16;" :: "r"(saddr), "l"(gaddr));
}
#define CP_COMMIT() asm volatile("cp.async.commit_group;" ::: "memory")
#define CP_WAIT(n)  asm volatile("cp.async.wait_group %0;" :: "n"(n) : "memory")

__device__ __forceinline__ void ldsm4(uint32_t* r, uint32_t addr) {
    asm volatile("ldmatrix.sync.aligned.m8n8.x4.shared.b16 {%0,%1,%2,%3}, [%4];"
                 : "=r"(r[0]), "=r"(r[1]), "=r"(r[2]), "=r"(r[3]) : "r"(addr));
}
__device__ __forceinline__ void mma16816(float* c, const uint32_t* a, const uint32_t* b) {
    asm volatile("mma.sync.aligned.m16n8k16.row.col.f32.bf16.bf16.f32 "
                 "{%0,%1,%2,%3}, {%4,%5,%6,%7}, {%8,%9}, {%0,%1,%2,%3};"
                 : "+f"(c[0]), "+f"(c[1]), "+f"(c[2]), "+f"(c[3])
                 : "r"(a[0]), "r"(a[1]), "r"(a[2]), "r"(a[3]),
                   "r"(b[0]), "r"(b[1]));
}

// ---------------- block reductions (blockDim == 256) -----------------------
__device__ __forceinline__ float blk_reduce_sum(float v, float* sh) {
    int lane = threadIdx.x & 31, w = threadIdx.x >> 5;
    #pragma unroll
    for (int o = 16; o; o >>= 1) v += __shfl_xor_sync(0xffffffffu, v, o);
    __syncthreads();
    if (lane == 0) sh[w] = v;
    __syncthreads();
    if (threadIdx.x == 0) {
        float r = 0.f;
        #pragma unroll
        for (int i = 0; i < 8; i++) r += sh[i];
        sh[0] = r;
    }
    __syncthreads();
    return sh[0];
}

// ---------------- GroupNorm (bf16 out) --------------------------------------
__global__ __launch_bounds__(256)
void gn_kernel(const float* __restrict__ x, const float* __restrict__ gsc,
               const float* __restrict__ gbi) {
    __shared__ float sh[8];
    int b = blockIdx.x >> 5;
    int g = blockIdx.x & 31;
    const size_t base = ((size_t)b * CCH + (size_t)g * CPG) * NTOK;
    const float* xp = x + base;
    const int total = CPG * NTOK;
    float s = 0.f, ss = 0.f;
    for (int i = threadIdx.x; i < total; i += 256) {
        float v = xp[i];
        s += v; ss += v * v;
    }
    s  = blk_reduce_sum(s,  sh);
    ss = blk_reduce_sum(ss, sh);
    const float inv_n = 1.f / (float)total;
    float mean = s * inv_n;
    float var  = ss * inv_n - mean * mean;
    float rstd = rsqrtf(var + EPSV);
    for (int i = threadIdx.x; i < total; i += 256) {
        int c = g * CPG + (i >> 12);
        g_hnb[base + i] = __float2bfloat16((xp[i] - mean) * rstd * gsc[c] + gbi[c]);
    }
}

// ---------------- bf16 transpose [C][N] -> [N][C] ----------------------------
__global__ __launch_bounds__(256)
void transpose_kernel(const bf16* __restrict__ src, bf16* __restrict__ dst) {
    __shared__ bf16 tile[64][65];
    const int b  = blockIdx.z;
    const int n0 = blockIdx.x * 64;
    const int c0 = blockIdx.y * 64;
    const bf16* sb = src + (size_t)b * CCH * NTOK;
    bf16*       db = dst + (size_t)b * NTOK * CCH;
    const int tx = threadIdx.x & 31, ty = threadIdx.x >> 5;
    #pragma unroll
    for (int j = 0; j < 8; j++) {
        uint32_t v = *(const uint32_t*)&sb[(size_t)(c0 + ty + 8 * j) * NTOK + n0 + tx * 2];
        __nv_bfloat162 v2 = *(__nv_bfloat162*)&v;
        tile[ty + 8 * j][tx * 2 + 0] = v2.x;
        tile[ty + 8 * j][tx * 2 + 1] = v2.y;
    }
    __syncthreads();
    #pragma unroll
    for (int j = 0; j < 8; j++) {
        int n = ty + 8 * j;
        __nv_bfloat162 v2;
        v2.x = tile[tx * 2 + 0][n];
        v2.y = tile[tx * 2 + 1][n];
        *(uint32_t*)&db[(size_t)(n0 + n) * CCH + c0 + tx * 2] = *(uint32_t*)&v2;
    }
}

// ---------------- fp32 -> bf16: all 4 weight matrices in one launch ----------
__global__ __launch_bounds__(256)
void w2bf_kernel(const float* __restrict__ w0, const float* __restrict__ w1,
                 const float* __restrict__ w2, const float* __restrict__ w3) {
    const int m = blockIdx.x >> 6;   // which matrix (64 blocks per matrix)
    const float* src = (m == 0) ? w0 : (m == 1) ? w1 : (m == 2) ? w2 : w3;
    bf16* dst = (m == 0) ? g_wqb : (m == 1) ? g_wkb : (m == 2) ? g_wvb : g_wpb;
    size_t i = (size_t)(blockIdx.x & 63) * 256 + threadIdx.x;   // float4 index
    float4 v = ((const float4*)src)[i];
    ((__nv_bfloat162*)dst)[2 * i + 0] = __floats2bfloat162_rn(v.x, v.y);
    ((__nv_bfloat162*)dst)[2 * i + 1] = __floats2bfloat162_rn(v.z, v.w);
}

// ---------------- NT bf16 GEMM: D[r][c] = scale*sum_k A[r][k]B[c][k] + ... ---
// Block tile 128(M) x 128(N) x 32(K). 256 thr = 8 warps (2 M x 4 N).
// cp.async 4-stage ring, SINGLE barrier per k-step:
//   wait(stage kt) -> sync -> prefetch stage kt+3 -> compute kt.
// Prefetch in iter kt overwrites stage (kt+3)&3 == (kt-1)&3, whose readers all
// passed this iteration's sync. 2 CTAs/SM.
#define TILE_ROW 40   // padded row elems (80 B) -> conflict-free ldmatrix
#define STAGE_BYTES (128 * TILE_ROW * 2)   // 10240
#define NSTAGE 4
#define SMEM_TOTAL_GEMM (2 * NSTAGE * STAGE_BYTES)   // 81920

__global__ __launch_bounds__(256, 2)
void mma_gemm(const bf16* __restrict__ A, const bf16* __restrict__ B, void* __restrict__ D,
              size_t aBatch, size_t bBatch, size_t dBatch,
              int astride, int bstride, int dstride, int ksteps, float scale,
              const float* __restrict__ bias, int biasMode,
              const float* __restrict__ resid, int outF32, int expOut) {
    extern __shared__ __align__(16) char smem[];
    const uint32_t sA = smem_u32(smem);
    const uint32_t sB = sA + NSTAGE * STAGE_BYTES;

    const int t    = threadIdx.x;
    const int lane = t & 31;
    const int wid  = t >> 5;
    const int wm   = wid & 1;
    const int wn   = wid >> 1;
    const int bz   = blockIdx.z;
    const int row0 = blockIdx.y * 128;
    const int col0 = blockIdx.x * 128;

    const bf16* Abase = A + (size_t)bz * aBatch + (size_t)row0 * astride;
    const bf16* Bbase = B + (size_t)bz * bBatch + (size_t)col0 * bstride;

    const int lrow = t >> 2;
    const int lcu  = t & 3;

    float acc[4][4][4];
    #pragma unroll
    for (int i = 0; i < 4; i++)
        #pragma unroll
        for (int j = 0; j < 4; j++)
            #pragma unroll
            for (int r = 0; r < 4; r++) acc[i][j][r] = 0.f;

    // prologue: chunks 0..NSTAGE-2, one commit-group each
    #pragma unroll
    for (int s = 0; s < NSTAGE - 1; s++) {
        if (s < ksteps) {
            const int k0 = s * 32;
            const uint32_t st = (uint32_t)s * STAGE_BYTES;
            #pragma unroll
            for (int i = 0; i < 2; i++) {
                int row = lrow + i * 64;
                uint32_t soff = st + (uint32_t)(row * TILE_ROW + lcu * 8) * 2;
                cp_async16(sA + soff, Abase + (size_t)row * astride + k0 + lcu * 8);
                cp_async16(sB + soff, Bbase + (size_t)row * bstride + k0 + lcu * 8);
            }
        }
        CP_COMMIT();
    }

    for (int kt = 0; kt < ksteps; kt++) {
        CP_WAIT(NSTAGE - 2);   // stage kt complete (keep newest NSTAGE-2 groups)
        __syncthreads();

        // prefetch stage kt+NSTAGE-1 (safe: its slot's readers passed the sync)
        {
            const int ci = kt + NSTAGE - 1;
            if (ci < ksteps) {
                const int k0 = ci * 32;
                const uint32_t st = (uint32_t)(ci & (NSTAGE - 1)) * STAGE_BYTES;
                #pragma unroll
                for (int i = 0; i < 2; i++) {
                    int row = lrow + i * 64;
                    uint32_t soff = st + (uint32_t)(row * TILE_ROW + lcu * 8) * 2;
                    cp_async16(sA + soff, Abase + (size_t)row * astride + k0 + lcu * 8);
                    cp_async16(sB + soff, Bbase + (size_t)row * bstride + k0 + lcu * 8);
                }
            }
            CP_COMMIT();       // always commit (empty group in tail)
        }

        const uint32_t aB = sA + (uint32_t)(kt & (NSTAGE - 1)) * STAGE_BYTES;
        const uint32_t bB = sB + (uint32_t)(kt & (NSTAGE - 1)) * STAGE_BYTES;
        #pragma unroll
        for (int ks = 0; ks < 2; ks++) {
            uint32_t afr[4][4], bfr[2][4];
            #pragma unroll
            for (int mf = 0; mf < 4; mf++) {
                uint32_t addr = aB + (uint32_t)((wm * 64 + mf * 16 + (lane & 15)) * (TILE_ROW * 2))
                              + (uint32_t)(ks * 32) + ((uint32_t)(lane >> 4) << 4);
                ldsm4(afr[mf], addr);
            }
            #pragma unroll
            for (int ng = 0; ng < 2; ng++) {
                uint32_t addr = bB + (uint32_t)((wn * 32 + ng * 16 + (lane & 7) + ((lane >> 4) & 1) * 8) * (TILE_ROW * 2))
                              + (uint32_t)(ks * 32) + ((uint32_t)((lane >> 3) & 1) << 4);
                ldsm4(bfr[ng], addr);
            }
            #pragma unroll
            for (int mf = 0; mf < 4; mf++)
                #pragma unroll
                for (int nf = 0; nf < 4; nf++)
                    mma16816(acc[mf][nf], afr[mf], &bfr[nf >> 1][(nf & 1) * 2]);
        }
    }

    // epilogue
    const float* residb = resid ? resid + (size_t)bz * dBatch : nullptr;
    #pragma unroll
    for (int mf = 0; mf < 4; mf++) {
        int rbase = row0 + wm * 64 + mf * 16 + (lane >> 2);
        #pragma unroll
        for (int nf = 0; nf < 4; nf++) {
            int c = col0 + wn * 32 + nf * 8 + (lane & 3) * 2;
            #pragma unroll
            for (int h = 0; h < 2; h++) {
                int r = rbase + h * 8;
                float v0 = acc[mf][nf][h * 2 + 0] * scale;
                float v1 = acc[mf][nf][h * 2 + 1] * scale;
                if (biasMode == 1)      { float bv = bias[r]; v0 += bv; v1 += bv; }
                else if (biasMode == 2) { v0 += bias[c]; v1 += bias[c + 1]; }
                size_t idx = (size_t)r * dstride + c;
                if (outF32) {
                    if (residb) { v0 += residb[idx]; v1 += residb[idx + 1]; }
                    float2 f; f.x = v0; f.y = v1;
                    *(float2*)((float*)D + (size_t)bz * dBatch + idx) = f;
                } else {
                    if (expOut) { v0 = __expf(v0); v1 = __expf(v1); }
                    *(__nv_bfloat162*)((bf16*)D + (size_t)bz * dBatch + idx) =
                        __floats2bfloat162_rn(v0, v1);
                }
            }
        }
    }
}

// ---------------- AV GEMM with inline row-sum normalization ------------------
// ht[n][o] = (1/rowsum_n) * sum_m expS[n][m] * vb[o][m]. Single-sync pipeline.
__global__ __launch_bounds__(256, 2)
void mma_av(const bf16* __restrict__ A, const bf16* __restrict__ B, bf16* __restrict__ D) {
    extern __shared__ __align__(16) char smem[];
    __shared__ float sumrow[128];
    const uint32_t sA = smem_u32(smem);
    const uint32_t sB = sA + NSTAGE * STAGE_BYTES;

    const int t    = threadIdx.x;
    const int lane = t & 31;
    const int wid  = t >> 5;
    const int wm   = wid & 1;
    const int wn   = wid >> 1;
    const int bz   = blockIdx.z;
    const int row0 = blockIdx.y * 128;
    const int col0 = blockIdx.x * 128;

    const bf16* Abase = A + (size_t)bz * NTOK * NTOK + (size_t)row0 * NTOK;
    const bf16* Bbase = B + (size_t)bz * CCH * NTOK + (size_t)col0 * NTOK;

    const int lrow = t >> 2;
    const int lcu  = t & 3;
    const int ksteps = NTOK / 32;   // 128

    float acc[4][4][4];
    #pragma unroll
    for (int i = 0; i < 4; i++)
        #pragma unroll
        for (int j = 0; j < 4; j++)
            #pragma unroll
            for (int r = 0; r < 4; r++) acc[i][j][r] = 0.f;
    float rs = 0.f;
    const int srow = t >> 1;            // 2 threads per A row for the row sum
    const int skoff = (t & 1) * 16;

    #pragma unroll
    for (int s = 0; s < NSTAGE - 1; s++) {
        const int k0 = s * 32;
        const uint32_t st = (uint32_t)s * STAGE_BYTES;
        #pragma unroll
        for (int i = 0; i < 2; i++) {
            int row = lrow + i * 64;
            uint32_t soff = st + (uint32_t)(row * TILE_ROW + lcu * 8) * 2;
            cp_async16(sA + soff, Abase + (size_t)row * NTOK + k0 + lcu * 8);
            cp_async16(sB + soff, Bbase + (size_t)row * NTOK + k0 + lcu * 8);
        }
        CP_COMMIT();
    }

    for (int kt = 0; kt < ksteps; kt++) {
        CP_WAIT(NSTAGE - 2);
        __syncthreads();

        {
            const int ci = kt + NSTAGE - 1;
            if (ci < ksteps) {
                const int k0 = ci * 32;
                const uint32_t st = (uint32_t)(ci & (NSTAGE - 1)) * STAGE_BYTES;
                #pragma unroll
                for (int i = 0; i < 2; i++) {
                    int row = lrow + i * 64;
                    uint32_t soff = st + (uint32_t)(row * TILE_ROW + lcu * 8) * 2;
                    cp_async16(sA + soff, Abase + (size_t)row * NTOK + k0 + lcu * 8);
                    cp_async16(sB + soff, Bbase + (size_t)row * NTOK + k0 + lcu * 8);
                }
            }
            CP_COMMIT();
        }

        const uint32_t aB = sA + (uint32_t)(kt & (NSTAGE - 1)) * STAGE_BYTES;
        const uint32_t bB = sB + (uint32_t)(kt & (NSTAGE - 1)) * STAGE_BYTES;
        #pragma unroll
        for (int ks = 0; ks < 2; ks++) {
            uint32_t afr[4][4], bfr[2][4];
            #pragma unroll
            for (int mf = 0; mf < 4; mf++) {
                uint32_t addr = aB + (uint32_t)((wm * 64 + mf * 16 + (lane & 15)) * (TILE_ROW * 2))
                              + (uint32_t)(ks * 32) + ((uint32_t)(lane >> 4) << 4);
                ldsm4(afr[mf], addr);
            }
            #pragma unroll
            for (int ng = 0; ng < 2; ng++) {
                uint32_t addr = bB + (uint32_t)((wn * 32 + ng * 16 + (lane & 7) + ((lane >> 4) & 1) * 8) * (TILE_ROW * 2))
                              + (uint32_t)(ks * 32) + ((uint32_t)((lane >> 3) & 1) << 4);
                ldsm4(bfr[ng], addr);
            }
            #pragma unroll
            for (int mf = 0; mf < 4; mf++)
                #pragma unroll
                for (int nf = 0; nf < 4; nf++)
                    mma16816(acc[mf][nf], afr[mf], &bfr[nf >> 1][(nf & 1) * 2]);
        }

        // inline row-sum of this A (expS) stage; same-iteration read is safe:
        // the overwrite of this slot is issued only after the NEXT sync.
        {
            const bf16* arow = (const bf16*)(smem
                + (size_t)(kt & (NSTAGE - 1)) * STAGE_BYTES)
                + srow * TILE_ROW + skoff;
            float part = 0.f;
            #pragma unroll
            for (int j = 0; j < 8; j++) {
                __nv_bfloat162 u = *(const __nv_bfloat162*)&arow[2 * j];
                part += __bfloat162float(u.x) + __bfloat162float(u.y);
            }
            rs += part;
        }
    }

    // combine row-sum halves (lanes t, t^1 adjacent in same warp)
    rs += __shfl_xor_sync(0xffffffffu, rs, 1);
    __syncthreads();             // all reads of last stage done before reuse of sumrow
    if ((t & 1) == 0) sumrow[srow] = rs;
    __syncthreads();

    // epilogue: normalize rows, write bf16
    bf16* Db = D + (size_t)bz * NTOK * CCH;
    #pragma unroll
    for (int mf = 0; mf < 4; mf++) {
        int rloc = wm * 64 + mf * 16 + (lane >> 2);
        #pragma unroll
        for (int nf = 0; nf < 4; nf++) {
            int c = col0 + wn * 32 + nf * 8 + (lane & 3) * 2;
            #pragma unroll
            for (int h = 0; h < 2; h++) {
                int rl = rloc + h * 8;
                float inv = 1.f / sumrow[rl];
                float v0 = acc[mf][nf][h * 2 + 0] * inv;
                float v1 = acc[mf][nf][h * 2 + 1] * inv;
                *(__nv_bfloat162*)&Db[(size_t)(row0 + rl) * CCH + c] =
                    __floats2bfloat162_rn(v0, v1);
            }
        }
    }
}

// ---------------- launch ------------------------------------------------------
extern "C" void kernel_launch(void* const* d_in, const int* in_sizes, int n_in,
                              void* d_out, int out_size) {
    const float* x     = (const float*)d_in[0];
    const float* gns   = (const float*)d_in[1];
    const float* gnb   = (const float*)d_in[2];
    const float* wq    = (const float*)d_in[3];
    const float* bq    = (const float*)d_in[4];
    const float* wk    = (const float*)d_in[5];
    const float* bk    = (const float*)d_in[6];
    const float* wv    = (const float*)d_in[7];
    const float* bv    = (const float*)d_in[8];
    const float* wproj = (const float*)d_in[9];
    const float* bproj = (const float*)d_in[10];
    float* out = (float*)d_out;

    bf16 *hnb, *hnT, *qt, *kt, *vb, *ht, *p, *wqb, *wkb, *wvb, *wpb;
    cudaGetSymbolAddress((void**)&hnb, g_hnb);
    cudaGetSymbolAddress((void**)&hnT, g_hnT);
    cudaGetSymbolAddress((void**)&qt,  g_qt);
    cudaGetSymbolAddress((void**)&kt,  g_kt);
    cudaGetSymbolAddress((void**)&vb,  g_vb);
    cudaGetSymbolAddress((void**)&ht,  g_ht);
    cudaGetSymbolAddress((void**)&p,   g_p);
    cudaGetSymbolAddress((void**)&wqb, g_wqb);
    cudaGetSymbolAddress((void**)&wkb, g_wkb);
    cudaGetSymbolAddress((void**)&wvb, g_wvb);
    cudaGetSymbolAddress((void**)&wpb, g_wpb);

    cudaFuncSetAttribute(mma_gemm, cudaFuncAttributeMaxDynamicSharedMemorySize, SMEM_TOTAL_GEMM);
    cudaFuncSetAttribute(mma_av,   cudaFuncAttributeMaxDynamicSharedMemorySize, SMEM_TOTAL_GEMM);

    const size_t CN = (size_t)CCH * NTOK;
    const size_t NN = (size_t)NTOK * NTOK;

    // 1. GroupNorm -> bf16 [c][n]
    gn_kernel<<<BBATCH * NG, 256>>>(x, gns, gnb);

    // 2. transpose -> hnT [n][c]
    dim3 gt(NTOK / 64, CCH / 64, BBATCH);
    transpose_kernel<<<gt, 256>>>(hnb, hnT);

    // 3. all 4 weight matrices -> bf16 in one launch
    w2bf_kernel<<<256, 256>>>(wq, wk, wv, wproj);

    // 4. qt[n][o] = hnT . Wq^T + bq   (bias per-col)
    dim3 gq(CCH / 128, NTOK / 128, BBATCH);
    mma_gemm<<<gq, 256, SMEM_TOTAL_GEMM>>>(hnT, wqb, qt, CN, 0, CN, CCH, CCH, CCH, CCH / 32, 1.f, bq, 2, nullptr, 0, 0);
    mma_gemm<<<gq, 256, SMEM_TOTAL_GEMM>>>(hnT, wkb, kt, CN, 0, CN, CCH, CCH, CCH, CCH / 32, 1.f, bk, 2, nullptr, 0, 0);

    // 5. vb[o][m] = Wv . hnT^T + bv   (bias per-row)
    dim3 gv(NTOK / 128, CCH / 128, BBATCH);
    mma_gemm<<<gv, 256, SMEM_TOTAL_GEMM>>>(wvb, hnT, vb, 0, CN, CN, CCH, CCH, NTOK, CCH / 32, 1.f, bv, 1, nullptr, 0, 0);

    // 6. expS[n][m] = exp((1/16) qt . kt^T)  -> bf16
    dim3 gs(NTOK / 128, NTOK / 128, BBATCH);
    mma_gemm<<<gs, 256, SMEM_TOTAL_GEMM>>>(qt, kt, p, CN, CN, NN, CCH, CCH, NTOK, CCH / 32, 0.0625f,
                          nullptr, 0, nullptr, 0, 1);

    // 7. ht[n][o] = softmax-normalized expS . vb^T  (row sums inline)
    dim3 gh(CCH / 128, NTOK / 128, BBATCH);
    mma_av<<<gh, 256, SMEM_TOTAL_GEMM>>>(p, vb, ht);

    // 8. out[o][n] = Wproj . ht^T + bproj + x   (fp32 out + residual)
    dim3 go(NTOK / 128, CCH / 128, BBATCH);
    mma_gemm<<<go, 256, SMEM_TOTAL_GEMM>>>(wpb, ht, out, 0, CN, CN, CCH, CCH, NTOK, CCH / 32, 1.f,
                          bproj, 1, x, 1, 0);
}

// round 13
// speedup vs baseline: 2.0044x; 1.0110x over previous
#include <cuda_runtime.h>
#include <cuda_bf16.h>
#include <cstddef>
#include <cstdint>

#define BBATCH 8
#define CCH    256
#define NTOK   4096     // 64*64
#define NG     32
#define CPG    8
#define EPSV   1e-6f

typedef __nv_bfloat16 bf16;

// ---------------- scratch (device globals; no allocation allowed) ----------
__device__ bf16  g_hnb[(size_t)BBATCH * CCH * NTOK];   // GN out [c][n]
__device__ bf16  g_hnT[(size_t)BBATCH * NTOK * CCH];   // GN out transposed [n][c]
__device__ bf16  g_qt [(size_t)BBATCH * NTOK * CCH];   // Q^T [n][o]
__device__ bf16  g_kt [(size_t)BBATCH * NTOK * CCH];   // K^T [m][o]
__device__ bf16  g_vb [(size_t)BBATCH * CCH * NTOK];   // V [o][m]
__device__ bf16  g_ht [(size_t)BBATCH * NTOK * CCH];   // attn out^T [n][o]
__device__ bf16  g_p  [(size_t)BBATCH * NTOK * NTOK];  // bf16 exp(S) (unnormalized)
__device__ bf16  g_wqb[CCH * CCH];
__device__ bf16  g_wkb[CCH * CCH];
__device__ bf16  g_wvb[CCH * CCH];
__device__ bf16  g_wpb[CCH * CCH];

// ================= low-level helpers ========================================
__device__ __forceinline__ uint32_t smem_u32(const void* p) {
    uint32_t a;
    asm("{ .reg .u64 t; cvta.to.shared.u64 t, %1; cvt.u32.u64 %0, t; }" : "=r"(a) : "l"(p));
    return a;
}
__device__ __forceinline__ void cp_async16(uint32_t saddr, const void* gaddr) {
    asm volatile("cp.async.cg.shared.global [%0], [%1], 16;" :: "r"(saddr), "l"(gaddr));
}
#define CP_COMMIT() asm volatile("cp.async.commit_group;" ::: "memory")
#define CP_WAIT(n)  asm volatile("cp.async.wait_group %0;" :: "n"(n) : "memory")

__device__ __forceinline__ void ldsm4(uint32_t* r, uint32_t addr) {
    asm volatile("ldmatrix.sync.aligned.m8n8.x4.shared.b16 {%0,%1,%2,%3}, [%4];"
                 : "=r"(r[0]), "=r"(r[1]), "=r"(r[2]), "=r"(r[3]) : "r"(addr));
}
__device__ __forceinline__ void mma16816(float* c, const uint32_t* a, const uint32_t* b) {
    asm volatile("mma.sync.aligned.m16n8k16.row.col.f32.bf16.bf16.f32 "
                 "{%0,%1,%2,%3}, {%4,%5,%6,%7}, {%8,%9}, {%0,%1,%2,%3};"
                 : "+f"(c[0]), "+f"(c[1]), "+f"(c[2]), "+f"(c[3])
                 : "r"(a[0]), "r"(a[1]), "r"(a[2]), "r"(a[3]),
                   "r"(b[0]), "r"(b[1]));
}

// ---------------- block reductions (blockDim == 256) -----------------------
__device__ __forceinline__ float blk_reduce_sum(float v, float* sh) {
    int lane = threadIdx.x & 31, w = threadIdx.x >> 5;
    #pragma unroll
    for (int o = 16; o; o >>= 1) v += __shfl_xor_sync(0xffffffffu, v, o);
    __syncthreads();
    if (lane == 0) sh[w] = v;
    __syncthreads();
    if (threadIdx.x == 0) {
        float r = 0.f;
        #pragma unroll
        for (int i = 0; i < 8; i++) r += sh[i];
        sh[0] = r;
    }
    __syncthreads();
    return sh[0];
}

// ---------------- GroupNorm (bf16 out) --------------------------------------
__global__ __launch_bounds__(256)
void gn_kernel(const float* __restrict__ x, const float* __restrict__ gsc,
               const float* __restrict__ gbi) {
    __shared__ float sh[8];
    int b = blockIdx.x >> 5;
    int g = blockIdx.x & 31;
    const size_t base = ((size_t)b * CCH + (size_t)g * CPG) * NTOK;
    const float* xp = x + base;
    const int total = CPG * NTOK;
    float s = 0.f, ss = 0.f;
    for (int i = threadIdx.x; i < total; i += 256) {
        float v = xp[i];
        s += v; ss += v * v;
    }
    s  = blk_reduce_sum(s,  sh);
    ss = blk_reduce_sum(ss, sh);
    const float inv_n = 1.f / (float)total;
    float mean = s * inv_n;
    float var  = ss * inv_n - mean * mean;
    float rstd = rsqrtf(var + EPSV);
    for (int i = threadIdx.x; i < total; i += 256) {
        int c = g * CPG + (i >> 12);
        g_hnb[base + i] = __float2bfloat16((xp[i] - mean) * rstd * gsc[c] + gbi[c]);
    }
}

// ---------------- bf16 transpose [C][N] -> [N][C] ----------------------------
__global__ __launch_bounds__(256)
void transpose_kernel(const bf16* __restrict__ src, bf16* __restrict__ dst) {
    __shared__ bf16 tile[64][65];
    const int b  = blockIdx.z;
    const int n0 = blockIdx.x * 64;
    const int c0 = blockIdx.y * 64;
    const bf16* sb = src + (size_t)b * CCH * NTOK;
    bf16*       db = dst + (size_t)b * NTOK * CCH;
    const int tx = threadIdx.x & 31, ty = threadIdx.x >> 5;
    #pragma unroll
    for (int j = 0; j < 8; j++) {
        uint32_t v = *(const uint32_t*)&sb[(size_t)(c0 + ty + 8 * j) * NTOK + n0 + tx * 2];
        __nv_bfloat162 v2 = *(__nv_bfloat162*)&v;
        tile[ty + 8 * j][tx * 2 + 0] = v2.x;
        tile[ty + 8 * j][tx * 2 + 1] = v2.y;
    }
    __syncthreads();
    #pragma unroll
    for (int j = 0; j < 8; j++) {
        int n = ty + 8 * j;
        __nv_bfloat162 v2;
        v2.x = tile[tx * 2 + 0][n];
        v2.y = tile[tx * 2 + 1][n];
        *(uint32_t*)&db[(size_t)(n0 + n) * CCH + c0 + tx * 2] = *(uint32_t*)&v2;
    }
}

// ---------------- fp32 -> bf16: all 4 weight matrices in one launch ----------
__global__ __launch_bounds__(256)
void w2bf_kernel(const float* __restrict__ w0, const float* __restrict__ w1,
                 const float* __restrict__ w2, const float* __restrict__ w3) {
    const int m = blockIdx.x >> 6;   // which matrix (64 blocks per matrix)
    const float* src = (m == 0) ? w0 : (m == 1) ? w1 : (m == 2) ? w2 : w3;
    bf16* dst = (m == 0) ? g_wqb : (m == 1) ? g_wkb : (m == 2) ? g_wvb : g_wpb;
    size_t i = (size_t)(blockIdx.x & 63) * 256 + threadIdx.x;   // float4 index
    float4 v = ((const float4*)src)[i];
    ((__nv_bfloat162*)dst)[2 * i + 0] = __floats2bfloat162_rn(v.x, v.y);
    ((__nv_bfloat162*)dst)[2 * i + 1] = __floats2bfloat162_rn(v.z, v.w);
}

// ---------------- NT bf16 GEMM: D[r][c] = scale*sum_k A[r][k]B[c][k] + ... ---
// Block tile 128(M) x 128(N) x 64(K). 256 thr = 8 warps (2 M x 4 N).
// cp.async 3-stage ring of 64-K chunks, SINGLE barrier per chunk:
//   wait(chunk kt) -> sync -> prefetch chunk kt+2 -> compute 4x k16 substeps.
// Rows padded to 144 B (stride 36 words == 4 mod 32 banks -> conflict-free
// ldmatrix). 2 CTAs/SM.
#define TILE_ROW 72   // padded row elems (144 B)
#define KCHUNK 64
#define STAGE_BYTES (128 * TILE_ROW * 2)   // 18432
#define NSTAGE 3
#define SMEM_TOTAL_GEMM (2 * NSTAGE * STAGE_BYTES)   // 110592

__global__ __launch_bounds__(256, 2)
void mma_gemm(const bf16* __restrict__ A, const bf16* __restrict__ B, void* __restrict__ D,
              size_t aBatch, size_t bBatch, size_t dBatch,
              int astride, int bstride, int dstride, int ksteps, float scale,
              const float* __restrict__ bias, int biasMode,
              const float* __restrict__ resid, int outF32, int expOut) {
    extern __shared__ __align__(16) char smem[];
    const uint32_t sA = smem_u32(smem);
    const uint32_t sB = sA + NSTAGE * STAGE_BYTES;

    const int t    = threadIdx.x;
    const int lane = t & 31;
    const int wid  = t >> 5;
    const int wm   = wid & 1;
    const int wn   = wid >> 1;
    const int bz   = blockIdx.z;
    const int row0 = blockIdx.y * 128;
    const int col0 = blockIdx.x * 128;

    const bf16* Abase = A + (size_t)bz * aBatch + (size_t)row0 * astride;
    const bf16* Bbase = B + (size_t)bz * bBatch + (size_t)col0 * bstride;

    const int lrow = t >> 2;   // 0..63; +64 in second iteration
    const int lcu  = t & 3;    // 16B chunk; +4 in second iteration (8 per row)

    float acc[4][4][4];
    #pragma unroll
    for (int i = 0; i < 4; i++)
        #pragma unroll
        for (int j = 0; j < 4; j++)
            #pragma unroll
            for (int r = 0; r < 4; r++) acc[i][j][r] = 0.f;

    // prologue: chunks 0..NSTAGE-2
    #pragma unroll
    for (int s = 0; s < NSTAGE - 1; s++) {
        if (s < ksteps) {
            const int k0 = s * KCHUNK;
            const uint32_t st = (uint32_t)s * STAGE_BYTES;
            #pragma unroll
            for (int i = 0; i < 2; i++) {
                int row = lrow + i * 64;
                #pragma unroll
                for (int j = 0; j < 2; j++) {
                    int cu = lcu + j * 4;
                    uint32_t soff = st + (uint32_t)(row * (TILE_ROW * 2) + cu * 16);
                    cp_async16(sA + soff, Abase + (size_t)row * astride + k0 + cu * 8);
                    cp_async16(sB + soff, Bbase + (size_t)row * bstride + k0 + cu * 8);
                }
            }
        }
        CP_COMMIT();
    }

    for (int kt = 0; kt < ksteps; kt++) {
        CP_WAIT(NSTAGE - 2);   // chunk kt complete
        __syncthreads();

        // prefetch chunk kt+NSTAGE-1 (slot (kt-1)%NSTAGE: readers passed sync)
        {
            const int ci = kt + NSTAGE - 1;
            if (ci < ksteps) {
                const int k0 = ci * KCHUNK;
                const uint32_t st = (uint32_t)(ci % NSTAGE) * STAGE_BYTES;
                #pragma unroll
                for (int i = 0; i < 2; i++) {
                    int row = lrow + i * 64;
                    #pragma unroll
                    for (int j = 0; j < 2; j++) {
                        int cu = lcu + j * 4;
                        uint32_t soff = st + (uint32_t)(row * (TILE_ROW * 2) + cu * 16);
                        cp_async16(sA + soff, Abase + (size_t)row * astride + k0 + cu * 8);
                        cp_async16(sB + soff, Bbase + (size_t)row * bstride + k0 + cu * 8);
                    }
                }
            }
            CP_COMMIT();       // always commit (empty group in tail)
        }

        const uint32_t aB = sA + (uint32_t)(kt % NSTAGE) * STAGE_BYTES;
        const uint32_t bB = sB + (uint32_t)(kt % NSTAGE) * STAGE_BYTES;
        #pragma unroll
        for (int ks = 0; ks < 4; ks++) {
            uint32_t afr[4][4], bfr[2][4];
            #pragma unroll
            for (int mf = 0; mf < 4; mf++) {
                uint32_t addr = aB + (uint32_t)((wm * 64 + mf * 16 + (lane & 15)) * (TILE_ROW * 2))
                              + (uint32_t)(ks * 32) + ((uint32_t)(lane >> 4) << 4);
                ldsm4(afr[mf], addr);
            }
            #pragma unroll
            for (int ng = 0; ng < 2; ng++) {
                uint32_t addr = bB + (uint32_t)((wn * 32 + ng * 16 + (lane & 7) + ((lane >> 4) & 1) * 8) * (TILE_ROW * 2))
                              + (uint32_t)(ks * 32) + ((uint32_t)((lane >> 3) & 1) << 4);
                ldsm4(bfr[ng], addr);
            }
            #pragma unroll
            for (int mf = 0; mf < 4; mf++)
                #pragma unroll
                for (int nf = 0; nf < 4; nf++)
                    mma16816(acc[mf][nf], afr[mf], &bfr[nf >> 1][(nf & 1) * 2]);
        }
    }

    // epilogue
    const float* residb = resid ? resid + (size_t)bz * dBatch : nullptr;
    #pragma unroll
    for (int mf = 0; mf < 4; mf++) {
        int rbase = row0 + wm * 64 + mf * 16 + (lane >> 2);
        #pragma unroll
        for (int nf = 0; nf < 4; nf++) {
            int c = col0 + wn * 32 + nf * 8 + (lane & 3) * 2;
            #pragma unroll
            for (int h = 0; h < 2; h++) {
                int r = rbase + h * 8;
                float v0 = acc[mf][nf][h * 2 + 0] * scale;
                float v1 = acc[mf][nf][h * 2 + 1] * scale;
                if (biasMode == 1)      { float bv = bias[r]; v0 += bv; v1 += bv; }
                else if (biasMode == 2) { v0 += bias[c]; v1 += bias[c + 1]; }
                size_t idx = (size_t)r * dstride + c;
                if (outF32) {
                    if (residb) { v0 += residb[idx]; v1 += residb[idx + 1]; }
                    float2 f; f.x = v0; f.y = v1;
                    *(float2*)((float*)D + (size_t)bz * dBatch + idx) = f;
                } else {
                    if (expOut) { v0 = __expf(v0); v1 = __expf(v1); }
                    *(__nv_bfloat162*)((bf16*)D + (size_t)bz * dBatch + idx) =
                        __floats2bfloat162_rn(v0, v1);
                }
            }
        }
    }
}

// ---------------- AV GEMM with inline row-sum normalization ------------------
// ht[n][o] = (1/rowsum_n) * sum_m expS[n][m] * vb[o][m]. 64-K chunks.
__global__ __launch_bounds__(256, 2)
void mma_av(const bf16* __restrict__ A, const bf16* __restrict__ B, bf16* __restrict__ D) {
    extern __shared__ __align__(16) char smem[];
    __shared__ float sumrow[128];
    const uint32_t sA = smem_u32(smem);
    const uint32_t sB = sA + NSTAGE * STAGE_BYTES;

    const int t    = threadIdx.x;
    const int lane = t & 31;
    const int wid  = t >> 5;
    const int wm   = wid & 1;
    const int wn   = wid >> 1;
    const int bz   = blockIdx.z;
    const int row0 = blockIdx.y * 128;
    const int col0 = blockIdx.x * 128;

    const bf16* Abase = A + (size_t)bz * NTOK * NTOK + (size_t)row0 * NTOK;
    const bf16* Bbase = B + (size_t)bz * CCH * NTOK + (size_t)col0 * NTOK;

    const int lrow = t >> 2;
    const int lcu  = t & 3;
    const int ksteps = NTOK / KCHUNK;   // 64

    float acc[4][4][4];
    #pragma unroll
    for (int i = 0; i < 4; i++)
        #pragma unroll
        for (int j = 0; j < 4; j++)
            #pragma unroll
            for (int r = 0; r < 4; r++) acc[i][j][r] = 0.f;
    float rs = 0.f;
    const int srow = t >> 1;            // 2 threads per A row for the row sum
    const int skoff = (t & 1) * 32;     // 32 elems (64 B) each

    #pragma unroll
    for (int s = 0; s < NSTAGE - 1; s++) {
        const int k0 = s * KCHUNK;
        const uint32_t st = (uint32_t)s * STAGE_BYTES;
        #pragma unroll
        for (int i = 0; i < 2; i++) {
            int row = lrow + i * 64;
            #pragma unroll
            for (int j = 0; j < 2; j++) {
                int cu = lcu + j * 4;
                uint32_t soff = st + (uint32_t)(row * (TILE_ROW * 2) + cu * 16);
                cp_async16(sA + soff, Abase + (size_t)row * NTOK + k0 + cu * 8);
                cp_async16(sB + soff, Bbase + (size_t)row * NTOK + k0 + cu * 8);
            }
        }
        CP_COMMIT();
    }

    for (int kt = 0; kt < ksteps; kt++) {
        CP_WAIT(NSTAGE - 2);
        __syncthreads();

        {
            const int ci = kt + NSTAGE - 1;
            if (ci < ksteps) {
                const int k0 = ci * KCHUNK;
                const uint32_t st = (uint32_t)(ci % NSTAGE) * STAGE_BYTES;
                #pragma unroll
                for (int i = 0; i < 2; i++) {
                    int row = lrow + i * 64;
                    #pragma unroll
                    for (int j = 0; j < 2; j++) {
                        int cu = lcu + j * 4;
                        uint32_t soff = st + (uint32_t)(row * (TILE_ROW * 2) + cu * 16);
                        cp_async16(sA + soff, Abase + (size_t)row * NTOK + k0 + cu * 8);
                        cp_async16(sB + soff, Bbase + (size_t)row * NTOK + k0 + cu * 8);
                    }
                }
            }
            CP_COMMIT();
        }

        const uint32_t aB = sA + (uint32_t)(kt % NSTAGE) * STAGE_BYTES;
        const uint32_t bB = sB + (uint32_t)(kt % NSTAGE) * STAGE_BYTES;
        #pragma unroll
        for (int ks = 0; ks < 4; ks++) {
            uint32_t afr[4][4], bfr[2][4];
            #pragma unroll
            for (int mf = 0; mf < 4; mf++) {
                uint32_t addr = aB + (uint32_t)((wm * 64 + mf * 16 + (lane & 15)) * (TILE_ROW * 2))
                              + (uint32_t)(ks * 32) + ((uint32_t)(lane >> 4) << 4);
                ldsm4(afr[mf], addr);
            }
            #pragma unroll
            for (int ng = 0; ng < 2; ng++) {
                uint32_t addr = bB + (uint32_t)((wn * 32 + ng * 16 + (lane & 7) + ((lane >> 4) & 1) * 8) * (TILE_ROW * 2))
                              + (uint32_t)(ks * 32) + ((uint32_t)((lane >> 3) & 1) << 4);
                ldsm4(bfr[ng], addr);
            }
            #pragma unroll
            for (int mf = 0; mf < 4; mf++)
                #pragma unroll
                for (int nf = 0; nf < 4; nf++)
                    mma16816(acc[mf][nf], afr[mf], &bfr[nf >> 1][(nf & 1) * 2]);
        }

        // inline row-sum of this expS chunk; safe: this slot's overwrite is
        // only issued after the NEXT sync.
        {
            const bf16* arow = (const bf16*)(smem
                + (size_t)(kt % NSTAGE) * STAGE_BYTES)
                + srow * TILE_ROW + skoff;
            float part = 0.f;
            #pragma unroll
            for (int j = 0; j < 16; j++) {
                __nv_bfloat162 u = *(const __nv_bfloat162*)&arow[2 * j];
                part += __bfloat162float(u.x) + __bfloat162float(u.y);
            }
            rs += part;
        }
    }

    // combine row-sum halves (lanes t, t^1 adjacent in same warp)
    rs += __shfl_xor_sync(0xffffffffu, rs, 1);
    __syncthreads();
    if ((t & 1) == 0) sumrow[srow] = rs;
    __syncthreads();

    // epilogue: normalize rows, write bf16
    bf16* Db = D + (size_t)bz * NTOK * CCH;
    #pragma unroll
    for (int mf = 0; mf < 4; mf++) {
        int rloc = wm * 64 + mf * 16 + (lane >> 2);
        #pragma unroll
        for (int nf = 0; nf < 4; nf++) {
            int c = col0 + wn * 32 + nf * 8 + (lane & 3) * 2;
            #pragma unroll
            for (int h = 0; h < 2; h++) {
                int rl = rloc + h * 8;
                float inv = 1.f / sumrow[rl];
                float v0 = acc[mf][nf][h * 2 + 0] * inv;
                float v1 = acc[mf][nf][h * 2 + 1] * inv;
                *(__nv_bfloat162*)&Db[(size_t)(row0 + rl) * CCH + c] =
                    __floats2bfloat162_rn(v0, v1);
            }
        }
    }
}

// ---------------- launch ------------------------------------------------------
extern "C" void kernel_launch(void* const* d_in, const int* in_sizes, int n_in,
                              void* d_out, int out_size) {
    const float* x     = (const float*)d_in[0];
    const float* gns   = (const float*)d_in[1];
    const float* gnb   = (const float*)d_in[2];
    const float* wq    = (const float*)d_in[3];
    const float* bq    = (const float*)d_in[4];
    const float* wk    = (const float*)d_in[5];
    const float* bk    = (const float*)d_in[6];
    const float* wv    = (const float*)d_in[7];
    const float* bv    = (const float*)d_in[8];
    const float* wproj = (const float*)d_in[9];
    const float* bproj = (const float*)d_in[10];
    float* out = (float*)d_out;

    bf16 *hnb, *hnT, *qt, *kt, *vb, *ht, *p, *wqb, *wkb, *wvb, *wpb;
    cudaGetSymbolAddress((void**)&hnb, g_hnb);
    cudaGetSymbolAddress((void**)&hnT, g_hnT);
    cudaGetSymbolAddress((void**)&qt,  g_qt);
    cudaGetSymbolAddress((void**)&kt,  g_kt);
    cudaGetSymbolAddress((void**)&vb,  g_vb);
    cudaGetSymbolAddress((void**)&ht,  g_ht);
    cudaGetSymbolAddress((void**)&p,   g_p);
    cudaGetSymbolAddress((void**)&wqb, g_wqb);
    cudaGetSymbolAddress((void**)&wkb, g_wkb);
    cudaGetSymbolAddress((void**)&wvb, g_wvb);
    cudaGetSymbolAddress((void**)&wpb, g_wpb);

    cudaFuncSetAttribute(mma_gemm, cudaFuncAttributeMaxDynamicSharedMemorySize, SMEM_TOTAL_GEMM);
    cudaFuncSetAttribute(mma_av,   cudaFuncAttributeMaxDynamicSharedMemorySize, SMEM_TOTAL_GEMM);

    const size_t CN = (size_t)CCH * NTOK;
    const size_t NN = (size_t)NTOK * NTOK;

    // 1. GroupNorm -> bf16 [c][n]
    gn_kernel<<<BBATCH * NG, 256>>>(x, gns, gnb);

    // 2. transpose -> hnT [n][c]
    dim3 gt(NTOK / 64, CCH / 64, BBATCH);
    transpose_kernel<<<gt, 256>>>(hnb, hnT);

    // 3. all 4 weight matrices -> bf16 in one launch
    w2bf_kernel<<<256, 256>>>(wq, wk, wv, wproj);

    // 4. qt[n][o] = hnT . Wq^T + bq   (bias per-col)
    dim3 gq(CCH / 128, NTOK / 128, BBATCH);
    mma_gemm<<<gq, 256, SMEM_TOTAL_GEMM>>>(hnT, wqb, qt, CN, 0, CN, CCH, CCH, CCH, CCH / KCHUNK, 1.f, bq, 2, nullptr, 0, 0);
    mma_gemm<<<gq, 256, SMEM_TOTAL_GEMM>>>(hnT, wkb, kt, CN, 0, CN, CCH, CCH, CCH, CCH / KCHUNK, 1.f, bk, 2, nullptr, 0, 0);

    // 5. vb[o][m] = Wv . hnT^T + bv   (bias per-row)
    dim3 gv(NTOK / 128, CCH / 128, BBATCH);
    mma_gemm<<<gv, 256, SMEM_TOTAL_GEMM>>>(wvb, hnT, vb, 0, CN, CN, CCH, CCH, NTOK, CCH / KCHUNK, 1.f, bv, 1, nullptr, 0, 0);

    // 6. expS[n][m] = exp((1/16) qt . kt^T)  -> bf16
    dim3 gs(NTOK / 128, NTOK / 128, BBATCH);
    mma_gemm<<<gs, 256, SMEM_TOTAL_GEMM>>>(qt, kt, p, CN, CN, NN, CCH, CCH, NTOK, CCH / KCHUNK, 0.0625f,
                          nullptr, 0, nullptr, 0, 1);

    // 7. ht[n][o] = softmax-normalized expS . vb^T  (row sums inline)
    dim3 gh(CCH / 128, NTOK / 128, BBATCH);
    mma_av<<<gh, 256, SMEM_TOTAL_GEMM>>>(p, vb, ht);

    // 8. out[o][n] = Wproj . ht^T + bproj + x   (fp32 out + residual)
    dim3 go(NTOK / 128, CCH / 128, BBATCH);
    mma_gemm<<<go, 256, SMEM_TOTAL_GEMM>>>(wpb, ht, out, 0, CN, CN, CCH, CCH, NTOK, CCH / KCHUNK, 1.f,
                          bproj, 1, x, 1, 0);
}